// round 1
// baseline (speedup 1.0000x reference)
#include <cuda_runtime.h>
#include <cuda_bf16.h>
#include <cstdint>

#define N_NODES 50000
#define N_EDGES 1600000
#define IN_C    1433
#define HID_C   128
#define OUT_C   47

// ---------------- scratch (static device globals; no runtime alloc) ----------
__device__ int   g_cnt[N_NODES];
__device__ int   g_rowptr[N_NODES + 1];
__device__ int   g_cursor[N_NODES];
__device__ int   g_srce[N_EDGES];
__device__ float g_dinv[N_NODES];
__device__ __align__(16) float g_bufA[(size_t)N_NODES * HID_C]; // hw (pre-agg); also hw3 as [N,47]
__device__ __align__(16) float g_bufB[(size_t)N_NODES * HID_C]; // h (post-agg)

// ---------------- graph preprocessing -----------------------------------
__global__ void k_zero_cnt() {
    int i = blockIdx.x * blockDim.x + threadIdx.x;
    if (i < N_NODES) g_cnt[i] = 0;
}

__global__ void k_hist(const int* __restrict__ ei) {
    int e = blockIdx.x * blockDim.x + threadIdx.x;
    if (e < N_EDGES) atomicAdd(&g_cnt[ei[N_EDGES + e]], 1);   // dst row
}

__global__ void k_dinv() {
    int i = blockIdx.x * blockDim.x + threadIdx.x;
    if (i < N_NODES) g_dinv[i] = rsqrtf((float)g_cnt[i] + 1.0f);  // +1 self-loop
}

// single-block exclusive scan of g_cnt -> g_rowptr / g_cursor (1024 threads)
__global__ void k_scan() {
    __shared__ int s_warp[32];
    int t = threadIdx.x, lane = t & 31, wid = t >> 5;
    int running = 0;
    for (int base = 0; base < N_NODES; base += 1024) {
        int i = base + t;
        int v = (i < N_NODES) ? g_cnt[i] : 0;
        int x = v;
        #pragma unroll
        for (int off = 1; off < 32; off <<= 1) {
            int y = __shfl_up_sync(0xffffffffu, x, off);
            if (lane >= off) x += y;
        }
        if (lane == 31) s_warp[wid] = x;
        __syncthreads();
        if (wid == 0) {
            int wx = s_warp[lane];
            #pragma unroll
            for (int off = 1; off < 32; off <<= 1) {
                int y = __shfl_up_sync(0xffffffffu, wx, off);
                if (lane >= off) wx += y;
            }
            s_warp[lane] = wx;
        }
        __syncthreads();
        int woff  = (wid > 0) ? s_warp[wid - 1] : 0;
        int incl  = x + woff;
        int total = s_warp[31];
        if (i < N_NODES) {
            int excl = running + incl - v;
            g_rowptr[i] = excl;
            g_cursor[i] = excl;
        }
        running += total;
        __syncthreads();
    }
    if (t == 0) g_rowptr[N_NODES] = running;
}

__global__ void k_fill(const int* __restrict__ ei) {
    int e = blockIdx.x * blockDim.x + threadIdx.x;
    if (e < N_EDGES) {
        int s = ei[e];
        int d = ei[N_EDGES + e];
        int p = atomicAdd(&g_cursor[d], 1);
        g_srce[p] = s;
    }
}

// ---------------- GEMM: C[M,Nact] = A[M,K] @ B[K,Nact]  (Nact <= 128) --------
// BM=64, BN=128 (padded), BK=16, 128 threads, 8x8 microtile.
// A = Aext if non-null else g_bufB. C = g_bufA. No bias/act (done in agg).
#define GBM 64
#define GBK 16

__global__ __launch_bounds__(128) void k_gemm(const float* __restrict__ Aext,
                                              const float* __restrict__ B,
                                              int M, int K, int Nact) {
    const float* A = Aext ? Aext : (const float*)g_bufB;
    float* C = g_bufA;

    __shared__ float As[GBK][GBM + 4];
    __shared__ float Bs[GBK][128];

    int t  = threadIdx.x;
    int tx = t & 15;       // 16 col-groups of 8  -> 128 cols
    int ty = t >> 4;       // 8  row-groups of 8  -> 64 rows
    int rowBase = blockIdx.x * GBM;

    float acc[8][8];
    #pragma unroll
    for (int i = 0; i < 8; i++)
        #pragma unroll
        for (int j = 0; j < 8; j++) acc[i][j] = 0.f;

    int ntiles = (K + GBK - 1) / GBK;
    bool k_vec = ((K & 3) == 0);

    for (int kt = 0; kt < ntiles; kt++) {
        int k0 = kt * GBK;

        // load A tile 64x16 (2 float4-equivalents per thread)
        #pragma unroll
        for (int u = 0; u < 2; u++) {
            int f4 = t * 2 + u;            // 0..255
            int r  = f4 >> 2;
            int kk = (f4 & 3) * 4;
            int grow = rowBase + r;
            float v0 = 0.f, v1 = 0.f, v2 = 0.f, v3 = 0.f;
            if (grow < M) {
                int kg = k0 + kk;
                const float* ap = A + (size_t)grow * K + kg;
                if (k_vec) {
                    if (kg < K) { float4 v = *(const float4*)ap; v0=v.x; v1=v.y; v2=v.z; v3=v.w; }
                } else {
                    if (kg + 3 < K)      { v0=ap[0]; v1=ap[1]; v2=ap[2]; v3=ap[3]; }
                    else {
                        if (kg + 0 < K) v0 = ap[0];
                        if (kg + 1 < K) v1 = ap[1];
                        if (kg + 2 < K) v2 = ap[2];
                        if (kg + 3 < K) v3 = ap[3];
                    }
                }
            }
            As[kk + 0][r] = v0; As[kk + 1][r] = v1;
            As[kk + 2][r] = v2; As[kk + 3][r] = v3;
        }

        // load B tile 16x128 (4 float4 per thread); pad cols >= Nact with 0
        #pragma unroll
        for (int u = 0; u < 4; u++) {
            int idx = t + u * 128;         // 0..511 float4 slots
            int r   = idx >> 5;            // 0..15
            int c4  = (idx & 31) * 4;
            float4 v = {0.f, 0.f, 0.f, 0.f};
            int kg = k0 + r;
            if (kg < K) {
                if (Nact == 128) {
                    v = *(const float4*)(B + (size_t)kg * 128 + c4);
                } else {
                    const float* bp = B + (size_t)kg * Nact;
                    if (c4 + 0 < Nact) v.x = bp[c4 + 0];
                    if (c4 + 1 < Nact) v.y = bp[c4 + 1];
                    if (c4 + 2 < Nact) v.z = bp[c4 + 2];
                    if (c4 + 3 < Nact) v.w = bp[c4 + 3];
                }
            }
            *(float4*)&Bs[r][c4] = v;
        }
        __syncthreads();

        #pragma unroll
        for (int kk = 0; kk < GBK; kk++) {
            float a[8], b[8];
            #pragma unroll
            for (int i = 0; i < 8; i++) a[i] = As[kk][ty * 8 + i];
            #pragma unroll
            for (int j = 0; j < 8; j++) b[j] = Bs[kk][tx * 8 + j];
            #pragma unroll
            for (int i = 0; i < 8; i++)
                #pragma unroll
                for (int j = 0; j < 8; j++) acc[i][j] += a[i] * b[j];
        }
        __syncthreads();
    }

    #pragma unroll
    for (int i = 0; i < 8; i++) {
        int grow = rowBase + ty * 8 + i;
        if (grow >= M) continue;
        if (Nact == 128) {
            float4 v0 = { acc[i][0], acc[i][1], acc[i][2], acc[i][3] };
            float4 v1 = { acc[i][4], acc[i][5], acc[i][6], acc[i][7] };
            *(float4*)(C + (size_t)grow * 128 + tx * 8)     = v0;
            *(float4*)(C + (size_t)grow * 128 + tx * 8 + 4) = v1;
        } else {
            #pragma unroll
            for (int j = 0; j < 8; j++) {
                int c = tx * 8 + j;
                if (c < Nact) C[(size_t)grow * Nact + c] = acc[i][j];
            }
        }
    }
}

// ---------------- aggregation: out[d] = sum_{e->d} hw[src]*norm + hw[d]*dinv_d^2 + b
// one warp per dst node; C=128 variant (float4 per lane)
template<bool RELU>
__global__ __launch_bounds__(128) void k_agg128(const float* __restrict__ bias) {
    const float* hw = g_bufA;
    float* out = g_bufB;
    __shared__ int   s_idx[4][32];
    __shared__ float s_wt [4][32];

    int w    = threadIdx.x >> 5;
    int lane = threadIdx.x & 31;
    int node = blockIdx.x * 4 + w;
    if (node >= N_NODES) return;

    int beg = g_rowptr[node];
    int end = g_rowptr[node + 1];
    float dd = g_dinv[node];

    float ax = 0.f, ay = 0.f, az = 0.f, aw = 0.f;

    for (int base = beg; base < end; base += 32) {
        int n = end - base; if (n > 32) n = 32;
        int si = 0; float swt = 0.f;
        if (lane < n) { si = g_srce[base + lane]; swt = g_dinv[si] * dd; }
        s_idx[w][lane] = si; s_wt[w][lane] = swt;
        __syncwarp();
        if (n == 32) {
            #pragma unroll 8
            for (int j = 0; j < 32; j++) {
                int ss = s_idx[w][j]; float ww = s_wt[w][j];
                float4 v = *(const float4*)(hw + (size_t)ss * 128 + lane * 4);
                ax += v.x * ww; ay += v.y * ww; az += v.z * ww; aw += v.w * ww;
            }
        } else {
            for (int j = 0; j < n; j++) {
                int ss = s_idx[w][j]; float ww = s_wt[w][j];
                float4 v = *(const float4*)(hw + (size_t)ss * 128 + lane * 4);
                ax += v.x * ww; ay += v.y * ww; az += v.z * ww; aw += v.w * ww;
            }
        }
        __syncwarp();
    }

    { // self-loop
        float ww = dd * dd;
        float4 v = *(const float4*)(hw + (size_t)node * 128 + lane * 4);
        ax += v.x * ww; ay += v.y * ww; az += v.z * ww; aw += v.w * ww;
    }
    float4 b = *(const float4*)(bias + lane * 4);
    ax += b.x; ay += b.y; az += b.z; aw += b.w;
    if (RELU) {
        ax = fmaxf(ax, 0.f); ay = fmaxf(ay, 0.f);
        az = fmaxf(az, 0.f); aw = fmaxf(aw, 0.f);
    }
    float4 r = { ax, ay, az, aw };
    *(float4*)(out + (size_t)node * 128 + lane * 4) = r;
}

// C=47 variant (final layer, no relu), writes d_out
__global__ __launch_bounds__(128) void k_agg47(const float* __restrict__ bias,
                                               float* __restrict__ out) {
    const float* hw = g_bufA;   // stride 47
    __shared__ int   s_idx[4][32];
    __shared__ float s_wt [4][32];

    int w    = threadIdx.x >> 5;
    int lane = threadIdx.x & 31;
    int node = blockIdx.x * 4 + w;
    if (node >= N_NODES) return;

    int beg = g_rowptr[node];
    int end = g_rowptr[node + 1];
    float dd = g_dinv[node];
    bool hi = (lane < OUT_C - 32);     // lanes 0..14 also cover cols 32..46

    float a0 = 0.f, a1 = 0.f;

    for (int base = beg; base < end; base += 32) {
        int n = end - base; if (n > 32) n = 32;
        int si = 0; float swt = 0.f;
        if (lane < n) { si = g_srce[base + lane]; swt = g_dinv[si] * dd; }
        s_idx[w][lane] = si; s_wt[w][lane] = swt;
        __syncwarp();
        for (int j = 0; j < n; j++) {
            int ss = s_idx[w][j]; float ww = s_wt[w][j];
            const float* row = hw + (size_t)ss * OUT_C;
            a0 += row[lane] * ww;
            if (hi) a1 += row[lane + 32] * ww;
        }
        __syncwarp();
    }
    { // self-loop
        float ww = dd * dd;
        const float* row = hw + (size_t)node * OUT_C;
        a0 += row[lane] * ww;
        if (hi) a1 += row[lane + 32] * ww;
    }
    a0 += bias[lane];
    if (hi) a1 += bias[lane + 32];

    out[(size_t)node * OUT_C + lane] = a0;
    if (hi) out[(size_t)node * OUT_C + lane + 32] = a1;
}

// ---------------- launch ------------------------------------------------
extern "C" void kernel_launch(void* const* d_in, const int* in_sizes, int n_in,
                              void* d_out, int out_size) {
    const float* x  = (const float*)d_in[0];
    const int*   ei = (const int*)  d_in[1];
    const float* W1 = (const float*)d_in[2];
    const float* b1 = (const float*)d_in[3];
    const float* W2 = (const float*)d_in[4];
    const float* b2 = (const float*)d_in[5];
    const float* W3 = (const float*)d_in[6];
    const float* b3 = (const float*)d_in[7];
    float* out = (float*)d_out;

    const int NB = (N_NODES + 255) / 256;
    const int EB = (N_EDGES + 255) / 256;

    // CSR build (per call; graph-replay safe)
    k_zero_cnt<<<NB, 256>>>();
    k_hist<<<EB, 256>>>(ei);
    k_dinv<<<NB, 256>>>();
    k_scan<<<1, 1024>>>();
    k_fill<<<EB, 256>>>(ei);

    const int gemmGrid = (N_NODES + GBM - 1) / GBM;
    const int aggGrid  = (N_NODES + 3) / 4;

    // layer 1
    k_gemm<<<gemmGrid, 128>>>(x, W1, N_NODES, IN_C, HID_C);
    k_agg128<true><<<aggGrid, 128>>>(b1);
    // layer 2
    k_gemm<<<gemmGrid, 128>>>(nullptr, W2, N_NODES, HID_C, HID_C);
    k_agg128<true><<<aggGrid, 128>>>(b2);
    // layer 3 (N padded to 128 in-kernel, stored compact at stride 47)
    k_gemm<<<gemmGrid, 128>>>(nullptr, W3, N_NODES, HID_C, OUT_C);
    k_agg47<<<aggGrid, 128>>>(b3, out);
}

// round 3
// speedup vs baseline: 1.1192x; 1.1192x over previous
#include <cuda_runtime.h>
#include <cuda_bf16.h>
#include <cstdint>

#define N_NODES 50000
#define N_EDGES 1600000
#define IN_C    1433
#define HID_C   128
#define OUT_C   47

// ---------------- scratch (static device globals; no runtime alloc) ----------
__device__ int   g_cnt[N_NODES];
__device__ int   g_rowptr[N_NODES + 1];
__device__ int   g_cursor[N_NODES];
__device__ int   g_srce[N_EDGES];
__device__ float g_dinv[N_NODES];
__device__ int   g_blksum[256];
__device__ int   g_blkoff[256];
__device__ __align__(16) float g_bufA[(size_t)N_NODES * HID_C]; // gemm out (pre-agg)
__device__ __align__(16) float g_bufB[(size_t)N_NODES * HID_C]; // agg out (post-act)

// ---------------- graph preprocessing -----------------------------------
__global__ void k_zero_cnt() {
    int i = blockIdx.x * blockDim.x + threadIdx.x;
    if (i < N_NODES) g_cnt[i] = 0;
}
__global__ void k_hist(const int* __restrict__ ei) {
    int e = blockIdx.x * blockDim.x + threadIdx.x;
    if (e < N_EDGES) atomicAdd(&g_cnt[ei[N_EDGES + e]], 1);
}
__global__ void k_dinv() {
    int i = blockIdx.x * blockDim.x + threadIdx.x;
    if (i < N_NODES) g_dinv[i] = rsqrtf((float)g_cnt[i] + 1.0f);
}

// 3-phase scan
__global__ void k_scan1() {
    __shared__ int sw[8];
    int i = blockIdx.x * 256 + threadIdx.x;
    int v = (i < N_NODES) ? g_cnt[i] : 0;
    int lane = threadIdx.x & 31, wid = threadIdx.x >> 5;
    #pragma unroll
    for (int o = 16; o > 0; o >>= 1) v += __shfl_down_sync(0xffffffffu, v, o);
    if (lane == 0) sw[wid] = v;
    __syncthreads();
    if (wid == 0) {
        int s = (lane < 8) ? sw[lane] : 0;
        #pragma unroll
        for (int o = 4; o > 0; o >>= 1) s += __shfl_down_sync(0xffu, s, o);
        if (lane == 0) g_blksum[blockIdx.x] = s;
    }
}
__global__ void k_scan2(int nblk) {
    __shared__ int sw[8];
    int t = threadIdx.x, lane = t & 31, wid = t >> 5;
    int v = (t < nblk) ? g_blksum[t] : 0;
    int x = v;
    #pragma unroll
    for (int o = 1; o < 32; o <<= 1) { int y = __shfl_up_sync(0xffffffffu, x, o); if (lane >= o) x += y; }
    if (lane == 31) sw[wid] = x;
    __syncthreads();
    if (wid == 0 && lane < 8) {
        int wx = sw[lane];
        #pragma unroll
        for (int o = 1; o < 8; o <<= 1) { int y = __shfl_up_sync(0xffu, wx, o); if (lane >= o) wx += y; }
        sw[lane] = wx;
    }
    __syncthreads();
    int excl = x - v + (wid ? sw[wid - 1] : 0);
    if (t < nblk) g_blkoff[t] = excl;
}
__global__ void k_scan3() {
    __shared__ int sw[8];
    int i = blockIdx.x * 256 + threadIdx.x;
    int t = threadIdx.x, lane = t & 31, wid = t >> 5;
    int v = (i < N_NODES) ? g_cnt[i] : 0;
    int x = v;
    #pragma unroll
    for (int o = 1; o < 32; o <<= 1) { int y = __shfl_up_sync(0xffffffffu, x, o); if (lane >= o) x += y; }
    if (lane == 31) sw[wid] = x;
    __syncthreads();
    if (wid == 0 && lane < 8) {
        int wx = sw[lane];
        #pragma unroll
        for (int o = 1; o < 8; o <<= 1) { int y = __shfl_up_sync(0xffu, wx, o); if (lane >= o) wx += y; }
        sw[lane] = wx;
    }
    __syncthreads();
    int excl = x - v + (wid ? sw[wid - 1] : 0) + g_blkoff[blockIdx.x];
    if (i < N_NODES) { g_rowptr[i] = excl; g_cursor[i] = excl; }
    if (i == 0) g_rowptr[N_NODES] = N_EDGES;
}
__global__ void k_fill(const int* __restrict__ ei) {
    int e = blockIdx.x * blockDim.x + threadIdx.x;
    if (e < N_EDGES) {
        int s = ei[e];
        int d = ei[N_EDGES + e];
        int p = atomicAdd(&g_cursor[d], 1);
        g_srce[p] = s;
    }
}

// ---------------- mma.sync bf16 GEMM (3-term split emulates fp32) ------------
// C[M,Nact] = A[M,K] @ B[K,Nact], Nact<=128. Tile 128x128, BK=32, 256 thr.
#define A_ST 40    // bf16 elems per A smem row (32 + 8 pad) -> conflict-free ldmatrix
#define B_ST 136   // bf16 elems per B smem row (128 + 8 pad)

__device__ __forceinline__ uint32_t smem_u32(const void* p) {
    uint32_t a;
    asm("{ .reg .u64 t; cvta.to.shared.u64 t, %1; cvt.u32.u64 %0, t; }" : "=r"(a) : "l"(p));
    return a;
}
__device__ __forceinline__ void ldmx4(uint32_t* r, uint32_t addr) {
    asm volatile("ldmatrix.sync.aligned.m8n8.x4.shared.b16 {%0,%1,%2,%3}, [%4];"
        : "=r"(r[0]), "=r"(r[1]), "=r"(r[2]), "=r"(r[3]) : "r"(addr));
}
__device__ __forceinline__ void ldmx2t(uint32_t* r, uint32_t addr) {
    asm volatile("ldmatrix.sync.aligned.m8n8.x2.trans.shared.b16 {%0,%1}, [%2];"
        : "=r"(r[0]), "=r"(r[1]) : "r"(addr));
}
__device__ __forceinline__ void mma16816(float* d, const uint32_t* a, const uint32_t* b) {
    asm volatile(
        "mma.sync.aligned.m16n8k16.row.col.f32.bf16.bf16.f32 "
        "{%0,%1,%2,%3}, {%4,%5,%6,%7}, {%8,%9}, {%0,%1,%2,%3};"
        : "+f"(d[0]), "+f"(d[1]), "+f"(d[2]), "+f"(d[3])
        : "r"(a[0]), "r"(a[1]), "r"(a[2]), "r"(a[3]), "r"(b[0]), "r"(b[1]));
}
__device__ __forceinline__ __nv_bfloat162 split_hi(float v0, float v1) {
    __nv_bfloat162 p; p.x = __float2bfloat16(v0); p.y = __float2bfloat16(v1); return p;
}
__device__ __forceinline__ __nv_bfloat162 split_lo(float v0, float v1, __nv_bfloat162 h) {
    __nv_bfloat162 p;
    p.x = __float2bfloat16(v0 - __bfloat162float(h.x));
    p.y = __float2bfloat16(v1 - __bfloat162float(h.y));
    return p;
}

__global__ __launch_bounds__(256, 2) void k_gemm_mma(
    const float* __restrict__ A, const float* __restrict__ B,
    float* __restrict__ C, int M, int K, int Nact)
{
    __shared__ __nv_bfloat16 sAh[128 * A_ST];
    __shared__ __nv_bfloat16 sAl[128 * A_ST];
    __shared__ __nv_bfloat16 sBh[32 * B_ST];
    __shared__ __nv_bfloat16 sBl[32 * B_ST];

    const int tid = threadIdx.x, lane = tid & 31, warp = tid >> 5;
    const int wm = warp >> 2, wn = warp & 3;        // 2 x 4 warp grid
    const int rowBase = blockIdx.x * 128;

    const uint32_t uAh = smem_u32(sAh), uAl = smem_u32(sAl);
    const uint32_t uBh = smem_u32(sBh), uBl = smem_u32(sBl);

    // per-lane ldmatrix offsets
    const int grp = lane >> 3;
    const uint32_t aLane = (uint32_t)((((grp & 1) * 8 + (lane & 7)) * A_ST + (grp >> 1) * 8) * 2);
    const uint32_t bLane = (uint32_t)(((lane & 15) * B_ST + wn * 32) * 2);

    float acc[4][4][4];
    #pragma unroll
    for (int i = 0; i < 4; i++)
        #pragma unroll
        for (int j = 0; j < 4; j++)
            #pragma unroll
            for (int r = 0; r < 4; r++) acc[i][j][r] = 0.f;

    const int NC = (K + 31) / 32;

    for (int c = 0; c < NC; c++) {
        const int k0 = c * 32;

        // --- A tile: 128 rows x 32 k, hi/lo split, pairs along k ---
        #pragma unroll
        for (int u = 0; u < 8; u++) {
            int idx = u * 256 + tid;            // 0..2047 pairs
            int kp  = (idx & 15) * 2;
            int m   = idx >> 4;
            int gm  = rowBase + m;
            int gk  = k0 + kp;
            float v0 = 0.f, v1 = 0.f;
            if (gm < M) {
                const float* ap = A + (size_t)gm * K;
                if (gk + 1 < K)      { v0 = ap[gk]; v1 = ap[gk + 1]; }
                else if (gk < K)     { v0 = ap[gk]; }
            }
            __nv_bfloat162 h = split_hi(v0, v1);
            __nv_bfloat162 l = split_lo(v0, v1, h);
            *(__nv_bfloat162*)&sAh[m * A_ST + kp] = h;
            *(__nv_bfloat162*)&sAl[m * A_ST + kp] = l;
        }
        // --- B tile: 32 k-rows x 128 n, pairs along n ---
        #pragma unroll
        for (int u = 0; u < 8; u++) {
            int idx = u * 256 + tid;            // 0..2047 pairs
            int n2  = (idx & 63) * 2;
            int kb  = idx >> 6;
            int gk  = k0 + kb;
            float v0 = 0.f, v1 = 0.f;
            if (gk < K) {
                const float* bp = B + (size_t)gk * Nact;
                if (n2 < Nact)     v0 = bp[n2];
                if (n2 + 1 < Nact) v1 = bp[n2 + 1];
            }
            __nv_bfloat162 h = split_hi(v0, v1);
            __nv_bfloat162 l = split_lo(v0, v1, h);
            *(__nv_bfloat162*)&sBh[kb * B_ST + n2] = h;
            *(__nv_bfloat162*)&sBl[kb * B_ST + n2] = l;
        }
        __syncthreads();

        #pragma unroll
        for (int ks = 0; ks < 2; ks++) {
            uint32_t bh[4][2], bl[4][2];
            #pragma unroll
            for (int nt = 0; nt < 4; nt++) {
                uint32_t bo = (uint32_t)(ks * 16 * B_ST * 2) + bLane + (uint32_t)(nt * 16);
                ldmx2t(bh[nt], uBh + bo);
                ldmx2t(bl[nt], uBl + bo);
            }
            #pragma unroll
            for (int mt = 0; mt < 4; mt++) {
                uint32_t ao = aLane + (uint32_t)(((wm * 64 + mt * 16) * A_ST + ks * 16) * 2);
                uint32_t ah[4], al[4];
                ldmx4(ah, uAh + ao);
                ldmx4(al, uAl + ao);
                #pragma unroll
                for (int nt = 0; nt < 4; nt++) mma16816(acc[mt][nt], ah, bh[nt]);
                #pragma unroll
                for (int nt = 0; nt < 4; nt++) mma16816(acc[mt][nt], ah, bl[nt]);
                #pragma unroll
                for (int nt = 0; nt < 4; nt++) mma16816(acc[mt][nt], al, bh[nt]);
            }
        }
        __syncthreads();
    }

    // ---- store C ----
    const int r = lane >> 2, cc = (lane & 3) * 2;
    #pragma unroll
    for (int mt = 0; mt < 4; mt++) {
        int m0 = rowBase + wm * 64 + mt * 16 + r;
        #pragma unroll
        for (int nt = 0; nt < 4; nt++) {
            int n0 = wn * 32 + nt * 8 + cc;
            if (Nact == 128) {
                if (m0 < M) {
                    float2 v = { acc[mt][nt][0], acc[mt][nt][1] };
                    *(float2*)(C + (size_t)m0 * 128 + n0) = v;
                }
                if (m0 + 8 < M) {
                    float2 v = { acc[mt][nt][2], acc[mt][nt][3] };
                    *(float2*)(C + (size_t)(m0 + 8) * 128 + n0) = v;
                }
            } else {
                if (m0 < M) {
                    if (n0 < Nact)     C[(size_t)m0 * Nact + n0]     = acc[mt][nt][0];
                    if (n0 + 1 < Nact) C[(size_t)m0 * Nact + n0 + 1] = acc[mt][nt][1];
                }
                if (m0 + 8 < M) {
                    if (n0 < Nact)     C[(size_t)(m0 + 8) * Nact + n0]     = acc[mt][nt][2];
                    if (n0 + 1 < Nact) C[(size_t)(m0 + 8) * Nact + n0 + 1] = acc[mt][nt][3];
                }
            }
        }
    }
}

// ---------------- aggregation -------------------------------------------
template<bool RELU>
__global__ __launch_bounds__(128) void k_agg128(const float* __restrict__ bias) {
    const float* hw = g_bufA;
    float* out = g_bufB;
    __shared__ int   s_idx[4][32];
    __shared__ float s_wt [4][32];

    int w    = threadIdx.x >> 5;
    int lane = threadIdx.x & 31;
    int node = blockIdx.x * 4 + w;
    if (node >= N_NODES) return;

    int beg = g_rowptr[node];
    int end = g_rowptr[node + 1];
    float dd = g_dinv[node];

    float ax = 0.f, ay = 0.f, az = 0.f, aw = 0.f;

    for (int base = beg; base < end; base += 32) {
        int n = end - base; if (n > 32) n = 32;
        int si = 0; float swt = 0.f;
        if (lane < n) { si = g_srce[base + lane]; swt = g_dinv[si] * dd; }
        s_idx[w][lane] = si; s_wt[w][lane] = swt;
        __syncwarp();
        if (n == 32) {
            #pragma unroll 8
            for (int j = 0; j < 32; j++) {
                int ss = s_idx[w][j]; float ww = s_wt[w][j];
                float4 v = *(const float4*)(hw + (size_t)ss * 128 + lane * 4);
                ax += v.x * ww; ay += v.y * ww; az += v.z * ww; aw += v.w * ww;
            }
        } else {
            for (int j = 0; j < n; j++) {
                int ss = s_idx[w][j]; float ww = s_wt[w][j];
                float4 v = *(const float4*)(hw + (size_t)ss * 128 + lane * 4);
                ax += v.x * ww; ay += v.y * ww; az += v.z * ww; aw += v.w * ww;
            }
        }
        __syncwarp();
    }

    {
        float ww = dd * dd;
        float4 v = *(const float4*)(hw + (size_t)node * 128 + lane * 4);
        ax += v.x * ww; ay += v.y * ww; az += v.z * ww; aw += v.w * ww;
    }
    float4 b = *(const float4*)(bias + lane * 4);
    ax += b.x; ay += b.y; az += b.z; aw += b.w;
    if (RELU) {
        ax = fmaxf(ax, 0.f); ay = fmaxf(ay, 0.f);
        az = fmaxf(az, 0.f); aw = fmaxf(aw, 0.f);
    }
    float4 rr = { ax, ay, az, aw };
    *(float4*)(out + (size_t)node * 128 + lane * 4) = rr;
}

__global__ __launch_bounds__(128) void k_agg47(const float* __restrict__ bias,
                                               float* __restrict__ out) {
    const float* hw = g_bufA;   // stride 47
    __shared__ int   s_idx[4][32];
    __shared__ float s_wt [4][32];

    int w    = threadIdx.x >> 5;
    int lane = threadIdx.x & 31;
    int node = blockIdx.x * 4 + w;
    if (node >= N_NODES) return;

    int beg = g_rowptr[node];
    int end = g_rowptr[node + 1];
    float dd = g_dinv[node];
    bool hi = (lane < OUT_C - 32);

    float a0 = 0.f, a1 = 0.f;

    for (int base = beg; base < end; base += 32) {
        int n = end - base; if (n > 32) n = 32;
        int si = 0; float swt = 0.f;
        if (lane < n) { si = g_srce[base + lane]; swt = g_dinv[si] * dd; }
        s_idx[w][lane] = si; s_wt[w][lane] = swt;
        __syncwarp();
        for (int j = 0; j < n; j++) {
            int ss = s_idx[w][j]; float ww = s_wt[w][j];
            const float* row = hw + (size_t)ss * OUT_C;
            a0 += row[lane] * ww;
            if (hi) a1 += row[lane + 32] * ww;
        }
        __syncwarp();
    }
    {
        float ww = dd * dd;
        const float* row = hw + (size_t)node * OUT_C;
        a0 += row[lane] * ww;
        if (hi) a1 += row[lane + 32] * ww;
    }
    a0 += bias[lane];
    if (hi) a1 += bias[lane + 32];

    out[(size_t)node * OUT_C + lane] = a0;
    if (hi) out[(size_t)node * OUT_C + lane + 32] = a1;
}

// ---------------- launch ------------------------------------------------
extern "C" void kernel_launch(void* const* d_in, const int* in_sizes, int n_in,
                              void* d_out, int out_size) {
    const float* x  = (const float*)d_in[0];
    const int*   ei = (const int*)  d_in[1];
    const float* W1 = (const float*)d_in[2];
    const float* b1 = (const float*)d_in[3];
    const float* W2 = (const float*)d_in[4];
    const float* b2 = (const float*)d_in[5];
    const float* W3 = (const float*)d_in[6];
    const float* b3 = (const float*)d_in[7];
    float* out = (float*)d_out;

    void *pA = nullptr, *pB = nullptr;
    cudaGetSymbolAddress(&pA, g_bufA);
    cudaGetSymbolAddress(&pB, g_bufB);
    float* bufA = (float*)pA;
    float* bufB = (float*)pB;

    const int NB = (N_NODES + 255) / 256;   // 196
    const int EB = (N_EDGES + 255) / 256;

    // CSR build
    k_zero_cnt<<<NB, 256>>>();
    k_hist<<<EB, 256>>>(ei);
    k_dinv<<<NB, 256>>>();
    k_scan1<<<NB, 256>>>();
    k_scan2<<<1, 256>>>(NB);
    k_scan3<<<NB, 256>>>();
    k_fill<<<EB, 256>>>(ei);

    const int gemmGrid = (N_NODES + 127) / 128;  // 391
    const int aggGrid  = (N_NODES + 3) / 4;

    // layer 1
    k_gemm_mma<<<gemmGrid, 256>>>(x, W1, bufA, N_NODES, IN_C, HID_C);
    k_agg128<true><<<aggGrid, 128>>>(b1);
    // layer 2
    k_gemm_mma<<<gemmGrid, 256>>>(bufB, W2, bufA, N_NODES, HID_C, HID_C);
    k_agg128<true><<<aggGrid, 128>>>(b2);
    // layer 3
    k_gemm_mma<<<gemmGrid, 256>>>(bufB, W3, bufA, N_NODES, HID_C, OUT_C);
    k_agg47<<<aggGrid, 128>>>(b3, out);
}

// round 5
// speedup vs baseline: 2.1409x; 1.9129x over previous
#include <cuda_runtime.h>
#include <cuda_bf16.h>
#include <cstdint>

#define N_NODES 50000
#define N_EDGES 1600000
#define IN_C    1433
#define HID_C   128
#define OUT_C   47

// ---------------- scratch (static device globals; no runtime alloc) ----------
__device__ int   g_cnt[N_NODES];
__device__ int   g_rowptr[N_NODES + 1];
__device__ int   g_cursor[N_NODES];
__device__ int   g_srce[N_EDGES];
__device__ float g_dinv[N_NODES];
__device__ int   g_blksum[256];
__device__ int   g_blkoff[256];
__device__ __align__(16) float g_bufA[(size_t)N_NODES * HID_C]; // gemm out (pre-agg)
__device__ __align__(16) float g_bufB[(size_t)N_NODES * HID_C]; // agg out (post-act)

// ---------------- graph preprocessing -----------------------------------
__global__ void k_zero_cnt() {
    int i = blockIdx.x * blockDim.x + threadIdx.x;
    if (i < N_NODES) g_cnt[i] = 0;
}
__global__ void k_hist(const int* __restrict__ ei) {
    int e = blockIdx.x * blockDim.x + threadIdx.x;
    if (e < N_EDGES) atomicAdd(&g_cnt[ei[N_EDGES + e]], 1);
}
__global__ void k_dinv() {
    int i = blockIdx.x * blockDim.x + threadIdx.x;
    if (i < N_NODES) g_dinv[i] = rsqrtf((float)g_cnt[i] + 1.0f);
}
__global__ void k_scan1() {
    __shared__ int sw[8];
    int i = blockIdx.x * 256 + threadIdx.x;
    int v = (i < N_NODES) ? g_cnt[i] : 0;
    int lane = threadIdx.x & 31, wid = threadIdx.x >> 5;
    #pragma unroll
    for (int o = 16; o > 0; o >>= 1) v += __shfl_down_sync(0xffffffffu, v, o);
    if (lane == 0) sw[wid] = v;
    __syncthreads();
    if (wid == 0) {
        int s = (lane < 8) ? sw[lane] : 0;
        #pragma unroll
        for (int o = 4; o > 0; o >>= 1) s += __shfl_down_sync(0xffu, s, o);
        if (lane == 0) g_blksum[blockIdx.x] = s;
    }
}
__global__ void k_scan2(int nblk) {
    __shared__ int sw[8];
    int t = threadIdx.x, lane = t & 31, wid = t >> 5;
    int v = (t < nblk) ? g_blksum[t] : 0;
    int x = v;
    #pragma unroll
    for (int o = 1; o < 32; o <<= 1) { int y = __shfl_up_sync(0xffffffffu, x, o); if (lane >= o) x += y; }
    if (lane == 31) sw[wid] = x;
    __syncthreads();
    if (wid == 0 && lane < 8) {
        int wx = sw[lane];
        #pragma unroll
        for (int o = 1; o < 8; o <<= 1) { int y = __shfl_up_sync(0xffu, wx, o); if (lane >= o) wx += y; }
        sw[lane] = wx;
    }
    __syncthreads();
    int excl = x - v + (wid ? sw[wid - 1] : 0);
    if (t < nblk) g_blkoff[t] = excl;
}
__global__ void k_scan3() {
    __shared__ int sw[8];
    int i = blockIdx.x * 256 + threadIdx.x;
    int t = threadIdx.x, lane = t & 31, wid = t >> 5;
    int v = (i < N_NODES) ? g_cnt[i] : 0;
    int x = v;
    #pragma unroll
    for (int o = 1; o < 32; o <<= 1) { int y = __shfl_up_sync(0xffffffffu, x, o); if (lane >= o) x += y; }
    if (lane == 31) sw[wid] = x;
    __syncthreads();
    if (wid == 0 && lane < 8) {
        int wx = sw[lane];
        #pragma unroll
        for (int o = 1; o < 8; o <<= 1) { int y = __shfl_up_sync(0xffu, wx, o); if (lane >= o) wx += y; }
        sw[lane] = wx;
    }
    __syncthreads();
    int excl = x - v + (wid ? sw[wid - 1] : 0) + g_blkoff[blockIdx.x];
    if (i < N_NODES) { g_rowptr[i] = excl; g_cursor[i] = excl; }
    if (i == 0) g_rowptr[N_NODES] = N_EDGES;
}
__global__ void k_fill(const int* __restrict__ ei) {
    int e = blockIdx.x * blockDim.x + threadIdx.x;
    if (e < N_EDGES) {
        int s = ei[e];
        int d = ei[N_EDGES + e];
        int p = atomicAdd(&g_cursor[d], 1);
        g_srce[p] = s;
    }
}

// ---------------- cp.async-pipelined mma.sync bf16 GEMM (3-term split) -------
#define A_ST 40    // bf16/row stride: 80 B  (16-aligned, conflict-free ldmatrix)
#define B_ST 136   // bf16/row stride: 272 B (16-aligned; 2-way on trans ldmatrix, OK)
// dynamic smem layout:
//   rawA[2][4096] f32 | rawB[2][4096] f32 | bfAh[5120] | bfAl[5120] | bfBh[4352] | bfBl[4352]
#define GEMM_SMEM (16384 * 4 + (5120 + 5120 + 4352 + 4352) * 2)

__device__ __forceinline__ uint32_t smem_u32(const void* p) {
    uint32_t a;
    asm("{ .reg .u64 t; cvta.to.shared.u64 t, %1; cvt.u32.u64 %0, t; }" : "=r"(a) : "l"(p));
    return a;
}
__device__ __forceinline__ void cpa4(uint32_t dst, const float* src, bool ok) {
    int sz = ok ? 4 : 0;
    asm volatile("cp.async.ca.shared.global [%0], [%1], 4, %2;" :: "r"(dst), "l"(src), "r"(sz));
}
__device__ __forceinline__ void cpa16(uint32_t dst, const float* src, bool ok) {
    int sz = ok ? 16 : 0;
    asm volatile("cp.async.cg.shared.global [%0], [%1], 16, %2;" :: "r"(dst), "l"(src), "r"(sz));
}
#define CP_COMMIT() asm volatile("cp.async.commit_group;" ::: "memory")
#define CP_WAIT1()  asm volatile("cp.async.wait_group 1;" ::: "memory")

__device__ __forceinline__ void ldmx4(uint32_t* r, uint32_t addr) {
    asm volatile("ldmatrix.sync.aligned.m8n8.x4.shared.b16 {%0,%1,%2,%3}, [%4];"
        : "=r"(r[0]), "=r"(r[1]), "=r"(r[2]), "=r"(r[3]) : "r"(addr));
}
__device__ __forceinline__ void ldmx2t(uint32_t* r, uint32_t addr) {
    asm volatile("ldmatrix.sync.aligned.m8n8.x2.trans.shared.b16 {%0,%1}, [%2];"
        : "=r"(r[0]), "=r"(r[1]) : "r"(addr));
}
__device__ __forceinline__ void mma16816(float* d, const uint32_t* a, const uint32_t* b) {
    asm volatile(
        "mma.sync.aligned.m16n8k16.row.col.f32.bf16.bf16.f32 "
        "{%0,%1,%2,%3}, {%4,%5,%6,%7}, {%8,%9}, {%0,%1,%2,%3};"
        : "+f"(d[0]), "+f"(d[1]), "+f"(d[2]), "+f"(d[3])
        : "r"(a[0]), "r"(a[1]), "r"(a[2]), "r"(a[3]), "r"(b[0]), "r"(b[1]));
}
__device__ __forceinline__ __nv_bfloat162 split_hi(float v0, float v1) {
    __nv_bfloat162 p; p.x = __float2bfloat16(v0); p.y = __float2bfloat16(v1); return p;
}
__device__ __forceinline__ __nv_bfloat162 split_lo(float v0, float v1, __nv_bfloat162 h) {
    __nv_bfloat162 p;
    p.x = __float2bfloat16(v0 - __bfloat162float(h.x));
    p.y = __float2bfloat16(v1 - __bfloat162float(h.y));
    return p;
}

__global__ __launch_bounds__(256, 2) void k_gemm_mma(
    const float* __restrict__ A, const float* __restrict__ B,
    float* __restrict__ C, int M, int K, int Nact)
{
    extern __shared__ char smp[];
    float* rawA = (float*)smp;                         // [2][4096]
    float* rawB = rawA + 8192;                         // [2][4096]
    __nv_bfloat16* bfAh = (__nv_bfloat16*)(rawB + 8192);
    __nv_bfloat16* bfAl = bfAh + 128 * A_ST;
    __nv_bfloat16* bfBh = bfAl + 128 * A_ST;
    __nv_bfloat16* bfBl = bfBh + 32 * B_ST;

    const int tid = threadIdx.x, lane = tid & 31, warp = tid >> 5;
    const int wm = warp >> 2, wn = warp & 3;           // 2 x 4 warp grid
    const int rowBase = blockIdx.x * 128;

    const uint32_t uRawA = smem_u32(rawA), uRawB = smem_u32(rawB);
    const uint32_t uAh = smem_u32(bfAh), uAl = smem_u32(bfAl);
    const uint32_t uBh = smem_u32(bfBh), uBl = smem_u32(bfBl);

    const int grp = lane >> 3;
    const uint32_t aLane = (uint32_t)((((grp & 1) * 8 + (lane & 7)) * A_ST + (grp >> 1) * 8) * 2);
    const uint32_t bLane = (uint32_t)(((lane & 15) * B_ST + wn * 32) * 2);

    float acc[4][4][4];
    #pragma unroll
    for (int i = 0; i < 4; i++)
        #pragma unroll
        for (int j = 0; j < 4; j++)
            #pragma unroll
            for (int r = 0; r < 4; r++) acc[i][j][r] = 0.f;

    const int NC = (K + 31) / 32;

    // ---- issue cp.async for chunk c into stage s ----
    auto issue = [&](int c, int s) {
        const int k0 = c * 32;
        uint32_t dA = uRawA + (uint32_t)(s * 4096) * 4;
        uint32_t dB = uRawB + (uint32_t)(s * 4096) * 4;
        #pragma unroll
        for (int u = 0; u < 16; u++) {
            int idx = u * 256 + tid;
            int k = idx & 31, m = idx >> 5;
            int gm = rowBase + m, gk = k0 + k;
            bool ok = (gm < M) && (gk < K);
            const float* src = A + (size_t)(ok ? gm : 0) * K + (ok ? gk : 0);
            cpa4(dA + (uint32_t)(m * 32 + k) * 4, src, ok);
        }
        if (Nact == 128) {
            #pragma unroll
            for (int u = 0; u < 4; u++) {
                int idx = u * 256 + tid;
                int n4 = (idx & 31) * 4, kb = idx >> 5;
                int gk = k0 + kb;
                bool ok = (gk < K);
                const float* src = B + (size_t)(ok ? gk : 0) * 128 + n4;
                cpa16(dB + (uint32_t)(kb * 128 + n4) * 4, src, ok);
            }
        } else {
            #pragma unroll
            for (int u = 0; u < 16; u++) {
                int idx = u * 256 + tid;
                int n = idx & 127, kb = idx >> 7;
                int gk = k0 + kb;
                bool ok = (gk < K) && (n < Nact);
                const float* src = B + (size_t)(ok ? gk : 0) * Nact + (ok ? n : 0);
                cpa4(dB + (uint32_t)(kb * 128 + n) * 4, src, ok);
            }
        }
    };

    issue(0, 0);
    CP_COMMIT();

    for (int c = 0; c < NC; c++) {
        const int b = c & 1;
        if (c + 1 < NC) issue(c + 1, b ^ 1);
        CP_COMMIT();
        CP_WAIT1();
        __syncthreads();   // raw stage b complete & visible to all

        // ---- convert raw -> bf16 hi/lo (smem -> smem) ----
        const float* rA = rawA + b * 4096;
        const float* rB = rawB + b * 4096;
        #pragma unroll
        for (int u = 0; u < 8; u++) {
            int idx = u * 256 + tid;
            int kp = (idx & 15) * 2, m = idx >> 4;
            float2 v = *(const float2*)&rA[m * 32 + kp];
            __nv_bfloat162 h = split_hi(v.x, v.y);
            __nv_bfloat162 l = split_lo(v.x, v.y, h);
            *(__nv_bfloat162*)&bfAh[m * A_ST + kp] = h;
            *(__nv_bfloat162*)&bfAl[m * A_ST + kp] = l;
        }
        #pragma unroll
        for (int u = 0; u < 8; u++) {
            int idx = u * 256 + tid;
            int n2 = (idx & 63) * 2, kb = idx >> 6;
            float2 v = *(const float2*)&rB[kb * 128 + n2];
            __nv_bfloat162 h = split_hi(v.x, v.y);
            __nv_bfloat162 l = split_lo(v.x, v.y, h);
            *(__nv_bfloat162*)&bfBh[kb * B_ST + n2] = h;
            *(__nv_bfloat162*)&bfBl[kb * B_ST + n2] = l;
        }
        __syncthreads();   // bf16 tiles ready

        // ---- mma on bf16 tiles ----
        #pragma unroll
        for (int ks = 0; ks < 2; ks++) {
            uint32_t bh[4][2], bl[4][2];
            #pragma unroll
            for (int nt = 0; nt < 4; nt++) {
                uint32_t bo = (uint32_t)(ks * 16 * B_ST * 2) + bLane + (uint32_t)(nt * 16);
                ldmx2t(bh[nt], uBh + bo);
                ldmx2t(bl[nt], uBl + bo);
            }
            #pragma unroll
            for (int mt = 0; mt < 4; mt++) {
                uint32_t ao = aLane + (uint32_t)(((wm * 64 + mt * 16) * A_ST + ks * 16) * 2);
                uint32_t ah[4], al[4];
                ldmx4(ah, uAh + ao);
                ldmx4(al, uAl + ao);
                #pragma unroll
                for (int nt = 0; nt < 4; nt++) mma16816(acc[mt][nt], ah, bh[nt]);
                #pragma unroll
                for (int nt = 0; nt < 4; nt++) mma16816(acc[mt][nt], ah, bl[nt]);
                #pragma unroll
                for (int nt = 0; nt < 4; nt++) mma16816(acc[mt][nt], al, bh[nt]);
            }
        }
        __syncthreads();   // bf16 tiles consumed
    }

    // ---- store C ----
    const int r = lane >> 2, cc = (lane & 3) * 2;
    #pragma unroll
    for (int mt = 0; mt < 4; mt++) {
        int m0 = rowBase + wm * 64 + mt * 16 + r;
        #pragma unroll
        for (int nt = 0; nt < 4; nt++) {
            int n0 = wn * 32 + nt * 8 + cc;
            if (Nact == 128) {
                if (m0 < M) {
                    float2 v = { acc[mt][nt][0], acc[mt][nt][1] };
                    *(float2*)(C + (size_t)m0 * 128 + n0) = v;
                }
                if (m0 + 8 < M) {
                    float2 v = { acc[mt][nt][2], acc[mt][nt][3] };
                    *(float2*)(C + (size_t)(m0 + 8) * 128 + n0) = v;
                }
            } else {
                if (m0 < M) {
                    if (n0 < Nact)     C[(size_t)m0 * Nact + n0]     = acc[mt][nt][0];
                    if (n0 + 1 < Nact) C[(size_t)m0 * Nact + n0 + 1] = acc[mt][nt][1];
                }
                if (m0 + 8 < M) {
                    if (n0 < Nact)     C[(size_t)(m0 + 8) * Nact + n0]     = acc[mt][nt][2];
                    if (n0 + 1 < Nact) C[(size_t)(m0 + 8) * Nact + n0 + 1] = acc[mt][nt][3];
                }
            }
        }
    }
}

// ---------------- aggregation -------------------------------------------
template<bool RELU>
__global__ __launch_bounds__(128) void k_agg128(const float* __restrict__ bias) {
    const float* hw = g_bufA;
    float* out = g_bufB;
    __shared__ int   s_idx[4][32];
    __shared__ float s_wt [4][32];

    int w    = threadIdx.x >> 5;
    int lane = threadIdx.x & 31;
    int node = blockIdx.x * 4 + w;
    if (node >= N_NODES) return;

    int beg = g_rowptr[node];
    int end = g_rowptr[node + 1];
    float dd = g_dinv[node];

    float ax = 0.f, ay = 0.f, az = 0.f, aw = 0.f;

    for (int base = beg; base < end; base += 32) {
        int n = end - base; if (n > 32) n = 32;
        int si = 0; float swt = 0.f;
        if (lane < n) { si = g_srce[base + lane]; swt = g_dinv[si] * dd; }
        s_idx[w][lane] = si; s_wt[w][lane] = swt;
        __syncwarp();
        if (n == 32) {
            #pragma unroll 8
            for (int j = 0; j < 32; j++) {
                int ss = s_idx[w][j]; float ww = s_wt[w][j];
                float4 v = *(const float4*)(hw + (size_t)ss * 128 + lane * 4);
                ax += v.x * ww; ay += v.y * ww; az += v.z * ww; aw += v.w * ww;
            }
        } else {
            for (int j = 0; j < n; j++) {
                int ss = s_idx[w][j]; float ww = s_wt[w][j];
                float4 v = *(const float4*)(hw + (size_t)ss * 128 + lane * 4);
                ax += v.x * ww; ay += v.y * ww; az += v.z * ww; aw += v.w * ww;
            }
        }
        __syncwarp();
    }

    {
        float ww = dd * dd;
        float4 v = *(const float4*)(hw + (size_t)node * 128 + lane * 4);
        ax += v.x * ww; ay += v.y * ww; az += v.z * ww; aw += v.w * ww;
    }
    float4 b = *(const float4*)(bias + lane * 4);
    ax += b.x; ay += b.y; az += b.z; aw += b.w;
    if (RELU) {
        ax = fmaxf(ax, 0.f); ay = fmaxf(ay, 0.f);
        az = fmaxf(az, 0.f); aw = fmaxf(aw, 0.f);
    }
    float4 rr = { ax, ay, az, aw };
    *(float4*)(out + (size_t)node * 128 + lane * 4) = rr;
}

__global__ __launch_bounds__(128) void k_agg47(const float* __restrict__ bias,
                                               float* __restrict__ out) {
    const float* hw = g_bufA;   // stride 47
    __shared__ int   s_idx[4][32];
    __shared__ float s_wt [4][32];

    int w    = threadIdx.x >> 5;
    int lane = threadIdx.x & 31;
    int node = blockIdx.x * 4 + w;
    if (node >= N_NODES) return;

    int beg = g_rowptr[node];
    int end = g_rowptr[node + 1];
    float dd = g_dinv[node];
    bool hi = (lane < OUT_C - 32);

    float a0 = 0.f, a1 = 0.f;

    for (int base = beg; base < end; base += 32) {
        int n = end - base; if (n > 32) n = 32;
        int si = 0; float swt = 0.f;
        if (lane < n) { si = g_srce[base + lane]; swt = g_dinv[si] * dd; }
        s_idx[w][lane] = si; s_wt[w][lane] = swt;
        __syncwarp();
        for (int j = 0; j < n; j++) {
            int ss = s_idx[w][j]; float ww = s_wt[w][j];
            const float* row = hw + (size_t)ss * OUT_C;
            a0 += row[lane] * ww;
            if (hi) a1 += row[lane + 32] * ww;
        }
        __syncwarp();
    }
    {
        float ww = dd * dd;
        const float* row = hw + (size_t)node * OUT_C;
        a0 += row[lane] * ww;
        if (hi) a1 += row[lane + 32] * ww;
    }
    a0 += bias[lane];
    if (hi) a1 += bias[lane + 32];

    out[(size_t)node * OUT_C + lane] = a0;
    if (hi) out[(size_t)node * OUT_C + lane + 32] = a1;
}

// ---------------- launch ------------------------------------------------
extern "C" void kernel_launch(void* const* d_in, const int* in_sizes, int n_in,
                              void* d_out, int out_size) {
    const float* x  = (const float*)d_in[0];
    const int*   ei = (const int*)  d_in[1];
    const float* W1 = (const float*)d_in[2];
    const float* b1 = (const float*)d_in[3];
    const float* W2 = (const float*)d_in[4];
    const float* b2 = (const float*)d_in[5];
    const float* W3 = (const float*)d_in[6];
    const float* b3 = (const float*)d_in[7];
    float* out = (float*)d_out;

    void *pA = nullptr, *pB = nullptr;
    cudaGetSymbolAddress(&pA, g_bufA);
    cudaGetSymbolAddress(&pB, g_bufB);
    float* bufA = (float*)pA;
    float* bufB = (float*)pB;

    cudaFuncSetAttribute(k_gemm_mma, cudaFuncAttributeMaxDynamicSharedMemorySize, GEMM_SMEM);

    const int NB = (N_NODES + 255) / 256;   // 196
    const int EB = (N_EDGES + 255) / 256;
    const int gemmGrid = (N_NODES + 127) / 128;  // 391
    const int aggGrid  = (N_NODES + 3) / 4;

    // launches 0-2: cheap preproc (no CSR dependency for GEMM1)
    k_zero_cnt<<<NB, 256>>>();
    k_hist<<<EB, 256>>>(ei);
    k_dinv<<<NB, 256>>>();
    // launch 3: GEMM1 (profiled by ncu -s 5 -c 1)
    k_gemm_mma<<<gemmGrid, 256, GEMM_SMEM>>>(x, W1, bufA, N_NODES, IN_C, HID_C);
    // CSR build completes while GEMM result is consumed next
    k_scan1<<<NB, 256>>>();
    k_scan2<<<1, 256>>>(NB);
    k_scan3<<<NB, 256>>>();
    k_fill<<<EB, 256>>>(ei);
    // layer 1 aggregation
    k_agg128<true><<<aggGrid, 128>>>(b1);
    // layer 2
    k_gemm_mma<<<gemmGrid, 256, GEMM_SMEM>>>(bufB, W2, bufA, N_NODES, HID_C, HID_C);
    k_agg128<true><<<aggGrid, 128>>>(b2);
    // layer 3
    k_gemm_mma<<<gemmGrid, 256, GEMM_SMEM>>>(bufB, W3, bufA, N_NODES, HID_C, OUT_C);
    k_agg47<<<aggGrid, 128>>>(b3, out);
}

// round 6
// speedup vs baseline: 2.7090x; 1.2654x over previous
#include <cuda_runtime.h>
#include <cuda_bf16.h>
#include <cstdint>

#define N_NODES 50000
#define N_EDGES 1600000
#define IN_C    1433
#define HID_C   128
#define OUT_C   47

#define KP1 1440   // 45 chunks * 32
#define KP2 128
#define KP3 128

// ---------------- scratch (static device globals; no runtime alloc) ----------
__device__ int   g_cnt[N_NODES];
__device__ int   g_rowptr[N_NODES + 1];
__device__ int   g_cursor[N_NODES];
__device__ int   g_srce[N_EDGES];
__device__ float g_dinv[N_NODES];
__device__ int   g_blksum[256];
__device__ int   g_blkoff[256];
__device__ __align__(16) float g_bufA[(size_t)N_NODES * HID_C]; // gemm out (pre-agg)
__device__ __align__(16) float g_bufB[(size_t)N_NODES * HID_C]; // agg out (post-act)
// pre-converted weights, padded [KP][136] bf16 hi/lo
__device__ __align__(16) __nv_bfloat16 g_W1h[KP1 * 136];
__device__ __align__(16) __nv_bfloat16 g_W1l[KP1 * 136];
__device__ __align__(16) __nv_bfloat16 g_W2h[KP2 * 136];
__device__ __align__(16) __nv_bfloat16 g_W2l[KP2 * 136];
__device__ __align__(16) __nv_bfloat16 g_W3h[KP3 * 136];
__device__ __align__(16) __nv_bfloat16 g_W3l[KP3 * 136];

// ---------------- graph preprocessing -----------------------------------
__global__ void k_zero_cnt() {
    int i = blockIdx.x * blockDim.x + threadIdx.x;
    if (i < N_NODES) g_cnt[i] = 0;
}
__global__ void k_hist(const int* __restrict__ ei) {
    int e = blockIdx.x * blockDim.x + threadIdx.x;
    if (e < N_EDGES) atomicAdd(&g_cnt[ei[N_EDGES + e]], 1);
}
__global__ void k_dinv() {
    int i = blockIdx.x * blockDim.x + threadIdx.x;
    if (i < N_NODES) g_dinv[i] = rsqrtf((float)g_cnt[i] + 1.0f);
}
__global__ void k_scan1() {
    __shared__ int sw[8];
    int i = blockIdx.x * 256 + threadIdx.x;
    int v = (i < N_NODES) ? g_cnt[i] : 0;
    int lane = threadIdx.x & 31, wid = threadIdx.x >> 5;
    #pragma unroll
    for (int o = 16; o > 0; o >>= 1) v += __shfl_down_sync(0xffffffffu, v, o);
    if (lane == 0) sw[wid] = v;
    __syncthreads();
    if (wid == 0) {
        int s = (lane < 8) ? sw[lane] : 0;
        #pragma unroll
        for (int o = 4; o > 0; o >>= 1) s += __shfl_down_sync(0xffu, s, o);
        if (lane == 0) g_blksum[blockIdx.x] = s;
    }
}
__global__ void k_scan2(int nblk) {
    __shared__ int sw[8];
    int t = threadIdx.x, lane = t & 31, wid = t >> 5;
    int v = (t < nblk) ? g_blksum[t] : 0;
    int x = v;
    #pragma unroll
    for (int o = 1; o < 32; o <<= 1) { int y = __shfl_up_sync(0xffffffffu, x, o); if (lane >= o) x += y; }
    if (lane == 31) sw[wid] = x;
    __syncthreads();
    if (wid == 0 && lane < 8) {
        int wx = sw[lane];
        #pragma unroll
        for (int o = 1; o < 8; o <<= 1) { int y = __shfl_up_sync(0xffu, wx, o); if (lane >= o) wx += y; }
        sw[lane] = wx;
    }
    __syncthreads();
    int excl = x - v + (wid ? sw[wid - 1] : 0);
    if (t < nblk) g_blkoff[t] = excl;
}
__global__ void k_scan3() {
    __shared__ int sw[8];
    int i = blockIdx.x * 256 + threadIdx.x;
    int t = threadIdx.x, lane = t & 31, wid = t >> 5;
    int v = (i < N_NODES) ? g_cnt[i] : 0;
    int x = v;
    #pragma unroll
    for (int o = 1; o < 32; o <<= 1) { int y = __shfl_up_sync(0xffffffffu, x, o); if (lane >= o) x += y; }
    if (lane == 31) sw[wid] = x;
    __syncthreads();
    if (wid == 0 && lane < 8) {
        int wx = sw[lane];
        #pragma unroll
        for (int o = 1; o < 8; o <<= 1) { int y = __shfl_up_sync(0xffu, wx, o); if (lane >= o) wx += y; }
        sw[lane] = wx;
    }
    __syncthreads();
    int excl = x - v + (wid ? sw[wid - 1] : 0) + g_blkoff[blockIdx.x];
    if (i < N_NODES) { g_rowptr[i] = excl; g_cursor[i] = excl; }
    if (i == 0) g_rowptr[N_NODES] = N_EDGES;
}
__global__ void k_fill(const int* __restrict__ ei) {
    int e = blockIdx.x * blockDim.x + threadIdx.x;
    if (e < N_EDGES) {
        int s = ei[e];
        int d = ei[N_EDGES + e];
        int p = atomicAdd(&g_cursor[d], 1);
        g_srce[p] = s;
    }
}

// ---------------- weight prepass: fp32 W[K,Nact] -> bf16 hi/lo [KP][136] -----
__global__ void k_prepW(const float* __restrict__ W,
                        __nv_bfloat16* __restrict__ oh, __nv_bfloat16* __restrict__ ol,
                        int K, int Nact, int KP) {
    int i = blockIdx.x * 256 + threadIdx.x;
    if (i >= KP * 136) return;
    int k = i / 136, n = i - k * 136;
    float v = (k < K && n < Nact) ? W[(size_t)k * Nact + n] : 0.f;
    __nv_bfloat16 h = __float2bfloat16(v);
    oh[i] = h;
    ol[i] = __float2bfloat16(v - __bfloat162float(h));
}

// ---------------- pipelined mma.sync bf16 GEMM (3-term split) ----------------
// smem per stage: Ah[128*40] | Al[128*40] | Bh[32*136] | Bl[32*136]  (bf16)
#define A_ST 40
#define B_ST 136
#define OFF_AL 10240
#define OFF_BH 20480
#define OFF_BL 29184
#define STAGE_B 37888
#define GEMM_SMEM (2 * STAGE_B)

__device__ __forceinline__ uint32_t smem_u32(const void* p) {
    uint32_t a;
    asm("{ .reg .u64 t; cvta.to.shared.u64 t, %1; cvt.u32.u64 %0, t; }" : "=r"(a) : "l"(p));
    return a;
}
__device__ __forceinline__ void cpa16(uint32_t dst, const void* src) {
    asm volatile("cp.async.cg.shared.global [%0], [%1], 16;" :: "r"(dst), "l"(src));
}
#define CP_COMMIT() asm volatile("cp.async.commit_group;" ::: "memory")
#define CP_WAIT0()  asm volatile("cp.async.wait_group 0;" ::: "memory")

__device__ __forceinline__ void ldmx4(uint32_t* r, uint32_t addr) {
    asm volatile("ldmatrix.sync.aligned.m8n8.x4.shared.b16 {%0,%1,%2,%3}, [%4];"
        : "=r"(r[0]), "=r"(r[1]), "=r"(r[2]), "=r"(r[3]) : "r"(addr));
}
__device__ __forceinline__ void ldmx2t(uint32_t* r, uint32_t addr) {
    asm volatile("ldmatrix.sync.aligned.m8n8.x2.trans.shared.b16 {%0,%1}, [%2];"
        : "=r"(r[0]), "=r"(r[1]) : "r"(addr));
}
__device__ __forceinline__ void mma16816(float* d, const uint32_t* a, const uint32_t* b) {
    asm volatile(
        "mma.sync.aligned.m16n8k16.row.col.f32.bf16.bf16.f32 "
        "{%0,%1,%2,%3}, {%4,%5,%6,%7}, {%8,%9}, {%0,%1,%2,%3};"
        : "+f"(d[0]), "+f"(d[1]), "+f"(d[2]), "+f"(d[3])
        : "r"(a[0]), "r"(a[1]), "r"(a[2]), "r"(a[3]), "r"(b[0]), "r"(b[1]));
}

template<bool VEC4>
__global__ __launch_bounds__(256, 2) void k_gemm_mma(
    const float* __restrict__ A,
    const __nv_bfloat16* __restrict__ Wh, const __nv_bfloat16* __restrict__ Wl,
    float* __restrict__ C, int M, int K, int Nact)
{
    extern __shared__ char smp[];
    const uint32_t sbase = smem_u32(smp);

    const int tid = threadIdx.x, lane = tid & 31, warp = tid >> 5;
    const int wm = warp >> 2, wn = warp & 3;           // 2 x 4 warp grid
    const int rowBase = blockIdx.x * 128;

    const int grp = lane >> 3;
    const uint32_t aLane = (uint32_t)((((grp & 1) * 8 + (lane & 7)) * A_ST + (grp >> 1) * 8) * 2);
    const uint32_t bLane = (uint32_t)(((lane & 15) * B_ST + wn * 32) * 2);

    float acc[4][4][4];
    #pragma unroll
    for (int i = 0; i < 4; i++)
        #pragma unroll
        for (int j = 0; j < 4; j++)
            #pragma unroll
            for (int r = 0; r < 4; r++) acc[i][j][r] = 0.f;

    const int NC = (K + 31) / 32;
    float aReg[16];

    // ---- helpers ----
    auto copyB = [&](int c, uint32_t st) {   // linear cp.async of pre-converted B chunk
        const char* sH = (const char*)(Wh + (size_t)c * 32 * 136);
        const char* sL = (const char*)(Wl + (size_t)c * 32 * 136);
        uint32_t dH = st + OFF_BH, dL = st + OFF_BL;
        #pragma unroll
        for (int u = 0; u < 3; u++) {       // 544 16B-chunks, 256 threads
            int i = u * 256 + tid;
            if (i < 544) {
                cpa16(dH + (uint32_t)i * 16, sH + i * 16);
                cpa16(dL + (uint32_t)i * 16, sL + i * 16);
            }
        }
    };
    auto loadA = [&](int c) {
        const int k0 = c * 32;
        if (VEC4) {
            #pragma unroll
            for (int u = 0; u < 4; u++) {
                int idx = u * 256 + tid;
                int kq = (idx & 7) * 4, m = idx >> 3;
                int gm = rowBase + m;
                float4 v = {0.f, 0.f, 0.f, 0.f};
                if (gm < M) v = *(const float4*)(A + (size_t)gm * K + k0 + kq);
                aReg[u * 4 + 0] = v.x; aReg[u * 4 + 1] = v.y;
                aReg[u * 4 + 2] = v.z; aReg[u * 4 + 3] = v.w;
            }
        } else {
            #pragma unroll
            for (int u = 0; u < 16; u++) {
                int m = u * 8 + warp;
                int gm = rowBase + m, gk = k0 + lane;
                aReg[u] = (gm < M && gk < K) ? __ldg(&A[(size_t)gm * K + gk]) : 0.f;
            }
        }
    };
    auto convA = [&](uint32_t st) {
        __nv_bfloat16* bh = (__nv_bfloat16*)(smp + (st - sbase));
        __nv_bfloat16* bl = (__nv_bfloat16*)(smp + (st - sbase) + OFF_AL);
        if (VEC4) {
            #pragma unroll
            for (int u = 0; u < 4; u++) {
                int idx = u * 256 + tid;
                int kq = (idx & 7) * 4, m = idx >> 3;
                #pragma unroll
                for (int p = 0; p < 2; p++) {
                    float v0 = aReg[u * 4 + p * 2], v1 = aReg[u * 4 + p * 2 + 1];
                    __nv_bfloat162 h; h.x = __float2bfloat16(v0); h.y = __float2bfloat16(v1);
                    __nv_bfloat162 l;
                    l.x = __float2bfloat16(v0 - __bfloat162float(h.x));
                    l.y = __float2bfloat16(v1 - __bfloat162float(h.y));
                    *(__nv_bfloat162*)&bh[m * A_ST + kq + p * 2] = h;
                    *(__nv_bfloat162*)&bl[m * A_ST + kq + p * 2] = l;
                }
            }
        } else {
            #pragma unroll
            for (int u = 0; u < 16; u++) {
                int m = u * 8 + warp;
                float v = aReg[u];
                __nv_bfloat16 h = __float2bfloat16(v);
                bh[m * A_ST + lane] = h;
                bl[m * A_ST + lane] = __float2bfloat16(v - __bfloat162float(h));
            }
        }
    };

    // ---- prologue: fill stage 0 ----
    copyB(0, sbase);
    CP_COMMIT();
    loadA(0);
    convA(sbase);
    CP_WAIT0();

    for (int c = 0; c < NC; c++) {
        __syncthreads();                         // stage (c&1) published; stage (c+1)&1 free
        const uint32_t stN = sbase + (uint32_t)((c + 1) & 1) * STAGE_B;
        const bool more = (c + 1 < NC);
        if (more) { copyB(c + 1, stN); }
        CP_COMMIT();
        if (more) loadA(c + 1);

        // ---- mma on stage c ----
        const uint32_t st = sbase + (uint32_t)(c & 1) * STAGE_B;
        const uint32_t uAh = st, uAl = st + OFF_AL, uBh = st + OFF_BH, uBl = st + OFF_BL;
        #pragma unroll
        for (int ks = 0; ks < 2; ks++) {
            uint32_t bh[4][2], bl[4][2];
            #pragma unroll
            for (int nt = 0; nt < 4; nt++) {
                uint32_t bo = (uint32_t)(ks * 16 * B_ST * 2) + bLane + (uint32_t)(nt * 16);
                ldmx2t(bh[nt], uBh + bo);
                ldmx2t(bl[nt], uBl + bo);
            }
            #pragma unroll
            for (int mt = 0; mt < 4; mt++) {
                uint32_t ao = aLane + (uint32_t)(((wm * 64 + mt * 16) * A_ST + ks * 16) * 2);
                uint32_t ah[4], al[4];
                ldmx4(ah, uAh + ao);
                ldmx4(al, uAl + ao);
                #pragma unroll
                for (int nt = 0; nt < 4; nt++) mma16816(acc[mt][nt], ah, bh[nt]);
                #pragma unroll
                for (int nt = 0; nt < 4; nt++) mma16816(acc[mt][nt], ah, bl[nt]);
                #pragma unroll
                for (int nt = 0; nt < 4; nt++) mma16816(acc[mt][nt], al, bh[nt]);
            }
        }

        if (more) convA(stN);
        CP_WAIT0();                              // B(c+1) landed
    }

    // ---- store C ----
    const int r = lane >> 2, cc = (lane & 3) * 2;
    #pragma unroll
    for (int mt = 0; mt < 4; mt++) {
        int m0 = rowBase + wm * 64 + mt * 16 + r;
        #pragma unroll
        for (int nt = 0; nt < 4; nt++) {
            int n0 = wn * 32 + nt * 8 + cc;
            if (Nact == 128) {
                if (m0 < M) {
                    float2 v = { acc[mt][nt][0], acc[mt][nt][1] };
                    *(float2*)(C + (size_t)m0 * 128 + n0) = v;
                }
                if (m0 + 8 < M) {
                    float2 v = { acc[mt][nt][2], acc[mt][nt][3] };
                    *(float2*)(C + (size_t)(m0 + 8) * 128 + n0) = v;
                }
            } else {
                if (m0 < M) {
                    if (n0 < Nact)     C[(size_t)m0 * Nact + n0]     = acc[mt][nt][0];
                    if (n0 + 1 < Nact) C[(size_t)m0 * Nact + n0 + 1] = acc[mt][nt][1];
                }
                if (m0 + 8 < M) {
                    if (n0 < Nact)     C[(size_t)(m0 + 8) * Nact + n0]     = acc[mt][nt][2];
                    if (n0 + 1 < Nact) C[(size_t)(m0 + 8) * Nact + n0 + 1] = acc[mt][nt][3];
                }
            }
        }
    }
}

// ---------------- aggregation -------------------------------------------
template<bool RELU>
__global__ __launch_bounds__(128) void k_agg128(const float* __restrict__ bias) {
    const float* hw = g_bufA;
    float* out = g_bufB;
    __shared__ int   s_idx[4][32];
    __shared__ float s_wt [4][32];

    int w    = threadIdx.x >> 5;
    int lane = threadIdx.x & 31;
    int node = blockIdx.x * 4 + w;
    if (node >= N_NODES) return;

    int beg = g_rowptr[node];
    int end = g_rowptr[node + 1];
    float dd = g_dinv[node];

    float ax = 0.f, ay = 0.f, az = 0.f, aw = 0.f;

    for (int base = beg; base < end; base += 32) {
        int n = end - base; if (n > 32) n = 32;
        int si = 0; float swt = 0.f;
        if (lane < n) { si = g_srce[base + lane]; swt = g_dinv[si] * dd; }
        s_idx[w][lane] = si; s_wt[w][lane] = swt;
        __syncwarp();
        if (n == 32) {
            #pragma unroll 8
            for (int j = 0; j < 32; j++) {
                int ss = s_idx[w][j]; float ww = s_wt[w][j];
                float4 v = *(const float4*)(hw + (size_t)ss * 128 + lane * 4);
                ax += v.x * ww; ay += v.y * ww; az += v.z * ww; aw += v.w * ww;
            }
        } else {
            for (int j = 0; j < n; j++) {
                int ss = s_idx[w][j]; float ww = s_wt[w][j];
                float4 v = *(const float4*)(hw + (size_t)ss * 128 + lane * 4);
                ax += v.x * ww; ay += v.y * ww; az += v.z * ww; aw += v.w * ww;
            }
        }
        __syncwarp();
    }

    {
        float ww = dd * dd;
        float4 v = *(const float4*)(hw + (size_t)node * 128 + lane * 4);
        ax += v.x * ww; ay += v.y * ww; az += v.z * ww; aw += v.w * ww;
    }
    float4 b = *(const float4*)(bias + lane * 4);
    ax += b.x; ay += b.y; az += b.z; aw += b.w;
    if (RELU) {
        ax = fmaxf(ax, 0.f); ay = fmaxf(ay, 0.f);
        az = fmaxf(az, 0.f); aw = fmaxf(aw, 0.f);
    }
    float4 rr = { ax, ay, az, aw };
    *(float4*)(out + (size_t)node * 128 + lane * 4) = rr;
}

__global__ __launch_bounds__(128) void k_agg47(const float* __restrict__ bias,
                                               float* __restrict__ out) {
    const float* hw = g_bufA;   // stride 47
    __shared__ int   s_idx[4][32];
    __shared__ float s_wt [4][32];

    int w    = threadIdx.x >> 5;
    int lane = threadIdx.x & 31;
    int node = blockIdx.x * 4 + w;
    if (node >= N_NODES) return;

    int beg = g_rowptr[node];
    int end = g_rowptr[node + 1];
    float dd = g_dinv[node];
    bool hi = (lane < OUT_C - 32);

    float a0 = 0.f, a1 = 0.f;

    for (int base = beg; base < end; base += 32) {
        int n = end - base; if (n > 32) n = 32;
        int si = 0; float swt = 0.f;
        if (lane < n) { si = g_srce[base + lane]; swt = g_dinv[si] * dd; }
        s_idx[w][lane] = si; s_wt[w][lane] = swt;
        __syncwarp();
        for (int j = 0; j < n; j++) {
            int ss = s_idx[w][j]; float ww = s_wt[w][j];
            const float* row = hw + (size_t)ss * OUT_C;
            a0 += row[lane] * ww;
            if (hi) a1 += row[lane + 32] * ww;
        }
        __syncwarp();
    }
    {
        float ww = dd * dd;
        const float* row = hw + (size_t)node * OUT_C;
        a0 += row[lane] * ww;
        if (hi) a1 += row[lane + 32] * ww;
    }
    a0 += bias[lane];
    if (hi) a1 += bias[lane + 32];

    out[(size_t)node * OUT_C + lane] = a0;
    if (hi) out[(size_t)node * OUT_C + lane + 32] = a1;
}

// ---------------- launch ------------------------------------------------
extern "C" void kernel_launch(void* const* d_in, const int* in_sizes, int n_in,
                              void* d_out, int out_size) {
    const float* x  = (const float*)d_in[0];
    const int*   ei = (const int*)  d_in[1];
    const float* W1 = (const float*)d_in[2];
    const float* b1 = (const float*)d_in[3];
    const float* W2 = (const float*)d_in[4];
    const float* b2 = (const float*)d_in[5];
    const float* W3 = (const float*)d_in[6];
    const float* b3 = (const float*)d_in[7];
    float* out = (float*)d_out;

    void *pA, *pB, *p1h, *p1l, *p2h, *p2l, *p3h, *p3l;
    cudaGetSymbolAddress(&pA, g_bufA);
    cudaGetSymbolAddress(&pB, g_bufB);
    cudaGetSymbolAddress(&p1h, g_W1h); cudaGetSymbolAddress(&p1l, g_W1l);
    cudaGetSymbolAddress(&p2h, g_W2h); cudaGetSymbolAddress(&p2l, g_W2l);
    cudaGetSymbolAddress(&p3h, g_W3h); cudaGetSymbolAddress(&p3l, g_W3l);
    float* bufA = (float*)pA;
    float* bufB = (float*)pB;

    cudaFuncSetAttribute(k_gemm_mma<false>, cudaFuncAttributeMaxDynamicSharedMemorySize, GEMM_SMEM);
    cudaFuncSetAttribute(k_gemm_mma<true>,  cudaFuncAttributeMaxDynamicSharedMemorySize, GEMM_SMEM);

    const int NB = (N_NODES + 255) / 256;
    const int EB = (N_EDGES + 255) / 256;
    const int gemmGrid = (N_NODES + 127) / 128;  // 391
    const int aggGrid  = (N_NODES + 3) / 4;

    // launches 0-2
    k_zero_cnt<<<NB, 256>>>();
    k_hist<<<EB, 256>>>(ei);
    k_prepW<<<(KP1 * 136 + 255) / 256, 256>>>(W1, (__nv_bfloat16*)p1h, (__nv_bfloat16*)p1l, IN_C, HID_C, KP1);
    // launch 3: GEMM1 (profiled)
    k_gemm_mma<false><<<gemmGrid, 256, GEMM_SMEM>>>(x, (const __nv_bfloat16*)p1h, (const __nv_bfloat16*)p1l,
                                                    bufA, N_NODES, IN_C, HID_C);
    // CSR build
    k_dinv<<<NB, 256>>>();
    k_scan1<<<NB, 256>>>();
    k_scan2<<<1, 256>>>(NB);
    k_scan3<<<NB, 256>>>();
    k_fill<<<EB, 256>>>(ei);
    k_prepW<<<(KP2 * 136 + 255) / 256, 256>>>(W2, (__nv_bfloat16*)p2h, (__nv_bfloat16*)p2l, HID_C, HID_C, KP2);
    k_prepW<<<(KP3 * 136 + 255) / 256, 256>>>(W3, (__nv_bfloat16*)p3h, (__nv_bfloat16*)p3l, HID_C, OUT_C, KP3);
    // layer 1 agg
    k_agg128<true><<<aggGrid, 128>>>(b1);
    // layer 2
    k_gemm_mma<true><<<gemmGrid, 256, GEMM_SMEM>>>(bufB, (const __nv_bfloat16*)p2h, (const __nv_bfloat16*)p2l,
                                                   bufA, N_NODES, HID_C, HID_C);
    k_agg128<true><<<aggGrid, 128>>>(b2);
    // layer 3
    k_gemm_mma<true><<<gemmGrid, 256, GEMM_SMEM>>>(bufB, (const __nv_bfloat16*)p3h, (const __nv_bfloat16*)p3l,
                                                   bufA, N_NODES, HID_C, OUT_C);
    k_agg47<<<aggGrid, 128>>>(b3, out);
}

// round 7
// speedup vs baseline: 2.8979x; 1.0697x over previous
#include <cuda_runtime.h>
#include <cuda_bf16.h>
#include <cuda_fp16.h>
#include <cstdint>

#define N_NODES 50000
#define N_EDGES 1600000
#define IN_C    1433
#define HID_C   128
#define OUT_C   47

#define KP1 1440   // 45 chunks * 32
#define KP2 128
#define KP3 128

// ---------------- scratch (static device globals; no runtime alloc) ----------
__device__ int   g_cnt[N_NODES];
__device__ int   g_rowptr[N_NODES + 1];
__device__ int   g_cursor[N_NODES];
__device__ int   g_srce[N_EDGES];
__device__ float g_dinv[N_NODES];
__device__ int   g_blksum[256];
__device__ int   g_blkoff[256];
__device__ __align__(16) float  g_bufA[(size_t)N_NODES * HID_C]; // fp32 gemm3 out / agg in (stride 47)
__device__ __align__(16) float  g_bufB[(size_t)N_NODES * HID_C]; // fp32 agg out (gemm2/3 input)
__device__ __align__(16) __half g_bufH[(size_t)N_NODES * HID_C]; // fp16 gemm1/2 out (gather src)
// pre-converted weights, padded [KP][136] bf16 hi/lo
__device__ __align__(16) __nv_bfloat16 g_W1h[KP1 * 136];
__device__ __align__(16) __nv_bfloat16 g_W1l[KP1 * 136];
__device__ __align__(16) __nv_bfloat16 g_W2h[KP2 * 136];
__device__ __align__(16) __nv_bfloat16 g_W2l[KP2 * 136];
__device__ __align__(16) __nv_bfloat16 g_W3h[KP3 * 136];
__device__ __align__(16) __nv_bfloat16 g_W3l[KP3 * 136];

// ---------------- graph preprocessing -----------------------------------
__global__ void k_zero_cnt() {
    int i = blockIdx.x * blockDim.x + threadIdx.x;
    if (i < N_NODES) g_cnt[i] = 0;
}
__global__ void k_hist(const int* __restrict__ ei) {
    int e = blockIdx.x * blockDim.x + threadIdx.x;
    if (e < N_EDGES) atomicAdd(&g_cnt[ei[N_EDGES + e]], 1);
}
__global__ void k_scan1() {
    __shared__ int sw[8];
    int i = blockIdx.x * 256 + threadIdx.x;
    int v = (i < N_NODES) ? g_cnt[i] : 0;
    int lane = threadIdx.x & 31, wid = threadIdx.x >> 5;
    #pragma unroll
    for (int o = 16; o > 0; o >>= 1) v += __shfl_down_sync(0xffffffffu, v, o);
    if (lane == 0) sw[wid] = v;
    __syncthreads();
    if (wid == 0) {
        int s = (lane < 8) ? sw[lane] : 0;
        #pragma unroll
        for (int o = 4; o > 0; o >>= 1) s += __shfl_down_sync(0xffu, s, o);
        if (lane == 0) g_blksum[blockIdx.x] = s;
    }
}
__global__ void k_scan2(int nblk) {
    __shared__ int sw[8];
    int t = threadIdx.x, lane = t & 31, wid = t >> 5;
    int v = (t < nblk) ? g_blksum[t] : 0;
    int x = v;
    #pragma unroll
    for (int o = 1; o < 32; o <<= 1) { int y = __shfl_up_sync(0xffffffffu, x, o); if (lane >= o) x += y; }
    if (lane == 31) sw[wid] = x;
    __syncthreads();
    if (wid == 0 && lane < 8) {
        int wx = sw[lane];
        #pragma unroll
        for (int o = 1; o < 8; o <<= 1) { int y = __shfl_up_sync(0xffu, wx, o); if (lane >= o) wx += y; }
        sw[lane] = wx;
    }
    __syncthreads();
    int excl = x - v + (wid ? sw[wid - 1] : 0);
    if (t < nblk) g_blkoff[t] = excl;
}
__global__ void k_scan3() {   // also computes dinv
    __shared__ int sw[8];
    int i = blockIdx.x * 256 + threadIdx.x;
    int t = threadIdx.x, lane = t & 31, wid = t >> 5;
    int v = (i < N_NODES) ? g_cnt[i] : 0;
    int x = v;
    #pragma unroll
    for (int o = 1; o < 32; o <<= 1) { int y = __shfl_up_sync(0xffffffffu, x, o); if (lane >= o) x += y; }
    if (lane == 31) sw[wid] = x;
    __syncthreads();
    if (wid == 0 && lane < 8) {
        int wx = sw[lane];
        #pragma unroll
        for (int o = 1; o < 8; o <<= 1) { int y = __shfl_up_sync(0xffu, wx, o); if (lane >= o) wx += y; }
        sw[lane] = wx;
    }
    __syncthreads();
    int excl = x - v + (wid ? sw[wid - 1] : 0) + g_blkoff[blockIdx.x];
    if (i < N_NODES) {
        g_rowptr[i] = excl; g_cursor[i] = excl;
        g_dinv[i] = rsqrtf((float)v + 1.0f);
    }
    if (i == 0) g_rowptr[N_NODES] = N_EDGES;
}
__global__ void k_fill(const int* __restrict__ ei) {
    int e = blockIdx.x * blockDim.x + threadIdx.x;
    if (e < N_EDGES) {
        int s = ei[e];
        int d = ei[N_EDGES + e];
        int p = atomicAdd(&g_cursor[d], 1);
        g_srce[p] = s;
    }
}

// ---------------- weight prepass: fp32 W[K,Nact] -> bf16 hi/lo [KP][136] -----
__global__ void k_prepW(const float* __restrict__ W,
                        __nv_bfloat16* __restrict__ oh, __nv_bfloat16* __restrict__ ol,
                        int K, int Nact, int KP) {
    int i = blockIdx.x * 256 + threadIdx.x;
    if (i >= KP * 136) return;
    int k = i / 136, n = i - k * 136;
    float v = (k < K && n < Nact) ? W[(size_t)k * Nact + n] : 0.f;
    __nv_bfloat16 h = __float2bfloat16(v);
    oh[i] = h;
    ol[i] = __float2bfloat16(v - __bfloat162float(h));
}

// ---------------- pipelined mma.sync bf16 GEMM (3-term split) ----------------
#define A_ST 40
#define B_ST 136
#define OFF_AL 10240
#define OFF_BH 20480
#define OFF_BL 29184
#define STAGE_B 37888
#define GEMM_SMEM (2 * STAGE_B)

__device__ __forceinline__ uint32_t smem_u32(const void* p) {
    uint32_t a;
    asm("{ .reg .u64 t; cvta.to.shared.u64 t, %1; cvt.u32.u64 %0, t; }" : "=r"(a) : "l"(p));
    return a;
}
__device__ __forceinline__ void cpa16(uint32_t dst, const void* src) {
    asm volatile("cp.async.cg.shared.global [%0], [%1], 16;" :: "r"(dst), "l"(src));
}
#define CP_COMMIT() asm volatile("cp.async.commit_group;" ::: "memory")
#define CP_WAIT0()  asm volatile("cp.async.wait_group 0;" ::: "memory")

__device__ __forceinline__ void ldmx4(uint32_t* r, uint32_t addr) {
    asm volatile("ldmatrix.sync.aligned.m8n8.x4.shared.b16 {%0,%1,%2,%3}, [%4];"
        : "=r"(r[0]), "=r"(r[1]), "=r"(r[2]), "=r"(r[3]) : "r"(addr));
}
__device__ __forceinline__ void ldmx2t(uint32_t* r, uint32_t addr) {
    asm volatile("ldmatrix.sync.aligned.m8n8.x2.trans.shared.b16 {%0,%1}, [%2];"
        : "=r"(r[0]), "=r"(r[1]) : "r"(addr));
}
__device__ __forceinline__ void mma16816(float* d, const uint32_t* a, const uint32_t* b) {
    asm volatile(
        "mma.sync.aligned.m16n8k16.row.col.f32.bf16.bf16.f32 "
        "{%0,%1,%2,%3}, {%4,%5,%6,%7}, {%8,%9}, {%0,%1,%2,%3};"
        : "+f"(d[0]), "+f"(d[1]), "+f"(d[2]), "+f"(d[3])
        : "r"(a[0]), "r"(a[1]), "r"(a[2]), "r"(a[3]), "r"(b[0]), "r"(b[1]));
}

// VEC4: A rows 16B-vectorizable (K%4==0). CHALF: C stored fp16 (Nact==128 only).
template<bool VEC4, bool CHALF>
__global__ __launch_bounds__(256, 2) void k_gemm_mma(
    const float* __restrict__ A,
    const __nv_bfloat16* __restrict__ Wh, const __nv_bfloat16* __restrict__ Wl,
    void* __restrict__ Cv, int M, int K, int Nact)
{
    extern __shared__ char smp[];
    const uint32_t sbase = smem_u32(smp);

    const int tid = threadIdx.x, lane = tid & 31, warp = tid >> 5;
    const int wm = warp >> 2, wn = warp & 3;           // 2 x 4 warp grid
    const int rowBase = blockIdx.x * 128;

    const int grp = lane >> 3;
    const uint32_t aLane = (uint32_t)((((grp & 1) * 8 + (lane & 7)) * A_ST + (grp >> 1) * 8) * 2);
    const uint32_t bLane = (uint32_t)(((lane & 15) * B_ST + wn * 32) * 2);

    float acc[4][4][4];
    #pragma unroll
    for (int i = 0; i < 4; i++)
        #pragma unroll
        for (int j = 0; j < 4; j++)
            #pragma unroll
            for (int r = 0; r < 4; r++) acc[i][j][r] = 0.f;

    const int NC = (K + 31) / 32;
    float aReg[16];

    auto copyB = [&](int c, uint32_t st) {
        const char* sH = (const char*)(Wh + (size_t)c * 32 * 136);
        const char* sL = (const char*)(Wl + (size_t)c * 32 * 136);
        uint32_t dH = st + OFF_BH, dL = st + OFF_BL;
        #pragma unroll
        for (int u = 0; u < 3; u++) {
            int i = u * 256 + tid;
            if (i < 544) {
                cpa16(dH + (uint32_t)i * 16, sH + i * 16);
                cpa16(dL + (uint32_t)i * 16, sL + i * 16);
            }
        }
    };
    auto loadA = [&](int c) {
        const int k0 = c * 32;
        if (VEC4) {
            #pragma unroll
            for (int u = 0; u < 4; u++) {
                int idx = u * 256 + tid;
                int kq = (idx & 7) * 4, m = idx >> 3;
                int gm = rowBase + m;
                float4 v = {0.f, 0.f, 0.f, 0.f};
                if (gm < M) v = *(const float4*)(A + (size_t)gm * K + k0 + kq);
                aReg[u * 4 + 0] = v.x; aReg[u * 4 + 1] = v.y;
                aReg[u * 4 + 2] = v.z; aReg[u * 4 + 3] = v.w;
            }
        } else {
            #pragma unroll
            for (int u = 0; u < 16; u++) {
                int m = u * 8 + warp;
                int gm = rowBase + m, gk = k0 + lane;
                aReg[u] = (gm < M && gk < K) ? __ldg(&A[(size_t)gm * K + gk]) : 0.f;
            }
        }
    };
    auto convA = [&](uint32_t st) {
        __nv_bfloat16* bh = (__nv_bfloat16*)(smp + (st - sbase));
        __nv_bfloat16* bl = (__nv_bfloat16*)(smp + (st - sbase) + OFF_AL);
        if (VEC4) {
            #pragma unroll
            for (int u = 0; u < 4; u++) {
                int idx = u * 256 + tid;
                int kq = (idx & 7) * 4, m = idx >> 3;
                #pragma unroll
                for (int p = 0; p < 2; p++) {
                    float v0 = aReg[u * 4 + p * 2], v1 = aReg[u * 4 + p * 2 + 1];
                    __nv_bfloat162 h; h.x = __float2bfloat16(v0); h.y = __float2bfloat16(v1);
                    __nv_bfloat162 l;
                    l.x = __float2bfloat16(v0 - __bfloat162float(h.x));
                    l.y = __float2bfloat16(v1 - __bfloat162float(h.y));
                    *(__nv_bfloat162*)&bh[m * A_ST + kq + p * 2] = h;
                    *(__nv_bfloat162*)&bl[m * A_ST + kq + p * 2] = l;
                }
            }
        } else {
            #pragma unroll
            for (int u = 0; u < 16; u++) {
                int m = u * 8 + warp;
                float v = aReg[u];
                __nv_bfloat16 h = __float2bfloat16(v);
                bh[m * A_ST + lane] = h;
                bl[m * A_ST + lane] = __float2bfloat16(v - __bfloat162float(h));
            }
        }
    };

    copyB(0, sbase);
    CP_COMMIT();
    loadA(0);
    convA(sbase);
    CP_WAIT0();

    for (int c = 0; c < NC; c++) {
        __syncthreads();
        const uint32_t stN = sbase + (uint32_t)((c + 1) & 1) * STAGE_B;
        const bool more = (c + 1 < NC);
        if (more) { copyB(c + 1, stN); }
        CP_COMMIT();
        if (more) loadA(c + 1);

        const uint32_t st = sbase + (uint32_t)(c & 1) * STAGE_B;
        const uint32_t uAh = st, uAl = st + OFF_AL, uBh = st + OFF_BH, uBl = st + OFF_BL;
        #pragma unroll
        for (int ks = 0; ks < 2; ks++) {
            uint32_t bh[4][2], bl[4][2];
            #pragma unroll
            for (int nt = 0; nt < 4; nt++) {
                uint32_t bo = (uint32_t)(ks * 16 * B_ST * 2) + bLane + (uint32_t)(nt * 16);
                ldmx2t(bh[nt], uBh + bo);
                ldmx2t(bl[nt], uBl + bo);
            }
            #pragma unroll
            for (int mt = 0; mt < 4; mt++) {
                uint32_t ao = aLane + (uint32_t)(((wm * 64 + mt * 16) * A_ST + ks * 16) * 2);
                uint32_t ah[4], al[4];
                ldmx4(ah, uAh + ao);
                ldmx4(al, uAl + ao);
                #pragma unroll
                for (int nt = 0; nt < 4; nt++) mma16816(acc[mt][nt], ah, bh[nt]);
                #pragma unroll
                for (int nt = 0; nt < 4; nt++) mma16816(acc[mt][nt], ah, bl[nt]);
                #pragma unroll
                for (int nt = 0; nt < 4; nt++) mma16816(acc[mt][nt], al, bh[nt]);
            }
        }

        if (more) convA(stN);
        CP_WAIT0();
    }

    // ---- store C ----
    const int r = lane >> 2, cc = (lane & 3) * 2;
    #pragma unroll
    for (int mt = 0; mt < 4; mt++) {
        int m0 = rowBase + wm * 64 + mt * 16 + r;
        #pragma unroll
        for (int nt = 0; nt < 4; nt++) {
            int n0 = wn * 32 + nt * 8 + cc;
            if (CHALF) {               // Nact == 128 guaranteed
                __half* C = (__half*)Cv;
                if (m0 < M)
                    *(__half2*)(C + (size_t)m0 * 128 + n0) = __floats2half2_rn(acc[mt][nt][0], acc[mt][nt][1]);
                if (m0 + 8 < M)
                    *(__half2*)(C + (size_t)(m0 + 8) * 128 + n0) = __floats2half2_rn(acc[mt][nt][2], acc[mt][nt][3]);
            } else if (Nact == 128) {
                float* C = (float*)Cv;
                if (m0 < M) {
                    float2 v = { acc[mt][nt][0], acc[mt][nt][1] };
                    *(float2*)(C + (size_t)m0 * 128 + n0) = v;
                }
                if (m0 + 8 < M) {
                    float2 v = { acc[mt][nt][2], acc[mt][nt][3] };
                    *(float2*)(C + (size_t)(m0 + 8) * 128 + n0) = v;
                }
            } else {
                float* C = (float*)Cv;
                if (m0 < M) {
                    if (n0 < Nact)     C[(size_t)m0 * Nact + n0]     = acc[mt][nt][0];
                    if (n0 + 1 < Nact) C[(size_t)m0 * Nact + n0 + 1] = acc[mt][nt][1];
                }
                if (m0 + 8 < M) {
                    if (n0 < Nact)     C[(size_t)(m0 + 8) * Nact + n0]     = acc[mt][nt][2];
                    if (n0 + 1 < Nact) C[(size_t)(m0 + 8) * Nact + n0 + 1] = acc[mt][nt][3];
                }
            }
        }
    }
}

// ---------------- aggregation (fp16 gather, fp32 accum/output) ----------------
template<bool RELU>
__global__ __launch_bounds__(128) void k_agg128h(const float* __restrict__ bias) {
    const __half* hw = g_bufH;          // row stride 128 halfs (256 B)
    float* out = g_bufB;
    __shared__ int   s_idx[4][32];
    __shared__ float s_wt [4][32];

    int w    = threadIdx.x >> 5;
    int lane = threadIdx.x & 31;
    int node = blockIdx.x * 4 + w;
    if (node >= N_NODES) return;

    int beg = g_rowptr[node];
    int end = g_rowptr[node + 1];
    float dd = g_dinv[node];

    float ax = 0.f, ay = 0.f, az = 0.f, aw = 0.f;

    for (int base = beg; base < end; base += 32) {
        int n = end - base; if (n > 32) n = 32;
        int si = 0; float swt = 0.f;
        if (lane < n) { si = g_srce[base + lane]; swt = g_dinv[si] * dd; }
        s_idx[w][lane] = si; s_wt[w][lane] = swt;
        __syncwarp();
        if (n == 32) {
            #pragma unroll 8
            for (int j = 0; j < 32; j++) {
                int ss = s_idx[w][j]; float ww = s_wt[w][j];
                uint2 raw = *(const uint2*)(hw + (size_t)ss * 128 + lane * 4);
                float2 f0 = __half22float2(*(__half2*)&raw.x);
                float2 f1 = __half22float2(*(__half2*)&raw.y);
                ax += f0.x * ww; ay += f0.y * ww; az += f1.x * ww; aw += f1.y * ww;
            }
        } else {
            for (int j = 0; j < n; j++) {
                int ss = s_idx[w][j]; float ww = s_wt[w][j];
                uint2 raw = *(const uint2*)(hw + (size_t)ss * 128 + lane * 4);
                float2 f0 = __half22float2(*(__half2*)&raw.x);
                float2 f1 = __half22float2(*(__half2*)&raw.y);
                ax += f0.x * ww; ay += f0.y * ww; az += f1.x * ww; aw += f1.y * ww;
            }
        }
        __syncwarp();
    }

    {   // self-loop
        float ww = dd * dd;
        uint2 raw = *(const uint2*)(hw + (size_t)node * 128 + lane * 4);
        float2 f0 = __half22float2(*(__half2*)&raw.x);
        float2 f1 = __half22float2(*(__half2*)&raw.y);
        ax += f0.x * ww; ay += f0.y * ww; az += f1.x * ww; aw += f1.y * ww;
    }
    float4 b = *(const float4*)(bias + lane * 4);
    ax += b.x; ay += b.y; az += b.z; aw += b.w;
    if (RELU) {
        ax = fmaxf(ax, 0.f); ay = fmaxf(ay, 0.f);
        az = fmaxf(az, 0.f); aw = fmaxf(aw, 0.f);
    }
    float4 rr = { ax, ay, az, aw };
    *(float4*)(out + (size_t)node * 128 + lane * 4) = rr;
}

__global__ __launch_bounds__(128) void k_agg47(const float* __restrict__ bias,
                                               float* __restrict__ out) {
    const float* hw = g_bufA;   // stride 47
    __shared__ int   s_idx[4][32];
    __shared__ float s_wt [4][32];

    int w    = threadIdx.x >> 5;
    int lane = threadIdx.x & 31;
    int node = blockIdx.x * 4 + w;
    if (node >= N_NODES) return;

    int beg = g_rowptr[node];
    int end = g_rowptr[node + 1];
    float dd = g_dinv[node];
    bool hi = (lane < OUT_C - 32);

    float a0 = 0.f, a1 = 0.f;

    for (int base = beg; base < end; base += 32) {
        int n = end - base; if (n > 32) n = 32;
        int si = 0; float swt = 0.f;
        if (lane < n) { si = g_srce[base + lane]; swt = g_dinv[si] * dd; }
        s_idx[w][lane] = si; s_wt[w][lane] = swt;
        __syncwarp();
        for (int j = 0; j < n; j++) {
            int ss = s_idx[w][j]; float ww = s_wt[w][j];
            const float* row = hw + (size_t)ss * OUT_C;
            a0 += row[lane] * ww;
            if (hi) a1 += row[lane + 32] * ww;
        }
        __syncwarp();
    }
    {
        float ww = dd * dd;
        const float* row = hw + (size_t)node * OUT_C;
        a0 += row[lane] * ww;
        if (hi) a1 += row[lane + 32] * ww;
    }
    a0 += bias[lane];
    if (hi) a1 += bias[lane + 32];

    out[(size_t)node * OUT_C + lane] = a0;
    if (hi) out[(size_t)node * OUT_C + lane + 32] = a1;
}

// ---------------- launch ------------------------------------------------
extern "C" void kernel_launch(void* const* d_in, const int* in_sizes, int n_in,
                              void* d_out, int out_size) {
    const float* x  = (const float*)d_in[0];
    const int*   ei = (const int*)  d_in[1];
    const float* W1 = (const float*)d_in[2];
    const float* b1 = (const float*)d_in[3];
    const float* W2 = (const float*)d_in[4];
    const float* b2 = (const float*)d_in[5];
    const float* W3 = (const float*)d_in[6];
    const float* b3 = (const float*)d_in[7];
    float* out = (float*)d_out;

    void *pA, *pB, *pH, *p1h, *p1l, *p2h, *p2l, *p3h, *p3l;
    cudaGetSymbolAddress(&pA, g_bufA);
    cudaGetSymbolAddress(&pB, g_bufB);
    cudaGetSymbolAddress(&pH, g_bufH);
    cudaGetSymbolAddress(&p1h, g_W1h); cudaGetSymbolAddress(&p1l, g_W1l);
    cudaGetSymbolAddress(&p2h, g_W2h); cudaGetSymbolAddress(&p2l, g_W2l);
    cudaGetSymbolAddress(&p3h, g_W3h); cudaGetSymbolAddress(&p3l, g_W3l);
    float* bufA = (float*)pA;
    float* bufB = (float*)pB;

    cudaFuncSetAttribute((const void*)&k_gemm_mma<false, true>, cudaFuncAttributeMaxDynamicSharedMemorySize, GEMM_SMEM);
    cudaFuncSetAttribute((const void*)&k_gemm_mma<true,  true>, cudaFuncAttributeMaxDynamicSharedMemorySize, GEMM_SMEM);
    cudaFuncSetAttribute((const void*)&k_gemm_mma<true, false>, cudaFuncAttributeMaxDynamicSharedMemorySize, GEMM_SMEM);

    const int NB = (N_NODES + 255) / 256;
    const int EB = (N_EDGES + 255) / 256;
    const int gemmGrid = (N_NODES + 127) / 128;  // 391
    const int aggGrid  = (N_NODES + 3) / 4;

    // launches 0-2
    k_zero_cnt<<<NB, 256>>>();
    k_hist<<<EB, 256>>>(ei);
    k_prepW<<<(KP1 * 136 + 255) / 256, 256>>>(W1, (__nv_bfloat16*)p1h, (__nv_bfloat16*)p1l, IN_C, HID_C, KP1);
    // launch 3: GEMM1 (profiled) -> fp16 C
    k_gemm_mma<false, true><<<gemmGrid, 256, GEMM_SMEM>>>(x, (const __nv_bfloat16*)p1h, (const __nv_bfloat16*)p1l,
                                                          pH, N_NODES, IN_C, HID_C);
    // CSR build
    k_scan1<<<NB, 256>>>();
    k_scan2<<<1, 256>>>(NB);
    k_scan3<<<NB, 256>>>();
    k_fill<<<EB, 256>>>(ei);
    k_prepW<<<(KP2 * 136 + 255) / 256, 256>>>(W2, (__nv_bfloat16*)p2h, (__nv_bfloat16*)p2l, HID_C, HID_C, KP2);
    k_prepW<<<(KP3 * 136 + 255) / 256, 256>>>(W3, (__nv_bfloat16*)p3h, (__nv_bfloat16*)p3l, HID_C, OUT_C, KP3);
    // layer 1 agg (fp16 gather -> fp32 h)
    k_agg128h<true><<<aggGrid, 128>>>(b1);
    // layer 2 -> fp16 C
    k_gemm_mma<true, true><<<gemmGrid, 256, GEMM_SMEM>>>(bufB, (const __nv_bfloat16*)p2h, (const __nv_bfloat16*)p2l,
                                                         pH, N_NODES, HID_C, HID_C);
    k_agg128h<true><<<aggGrid, 128>>>(b2);
    // layer 3 -> fp32 C (stride 47)
    k_gemm_mma<true, false><<<gemmGrid, 256, GEMM_SMEM>>>(bufB, (const __nv_bfloat16*)p3h, (const __nv_bfloat16*)p3l,
                                                          pA, N_NODES, HID_C, OUT_C);
    k_agg47<<<aggGrid, 128>>>(b3, out);
}

// round 8
// speedup vs baseline: 3.4012x; 1.1737x over previous
#include <cuda_runtime.h>
#include <cuda_bf16.h>
#include <cuda_fp16.h>
#include <cstdint>

#define N_NODES 50000
#define N_EDGES 1600000
#define IN_C    1433
#define HID_C   128
#define OUT_C   47

#define KP1 1440   // 45 chunks * 32
#define KP2 128
#define KP3 128

// ---------------- scratch (static device globals; no runtime alloc) ----------
__device__ int   g_cnt[N_NODES];
__device__ int   g_rowptr[N_NODES + 1];
__device__ int   g_cursor[N_NODES];
__device__ int   g_srce[N_EDGES];
__device__ float g_dinv[N_NODES];
__device__ int   g_blksum[256];
__device__ int   g_blkoff[256];
__device__ __align__(16) float  g_bufA[(size_t)N_NODES * HID_C]; // fp32 gemm3 out (stride 47)
__device__ __align__(16) float  g_bufB[(size_t)N_NODES * HID_C]; // fp32 agg out (gemm2/3 input)
__device__ __align__(16) __half g_bufH[(size_t)N_NODES * HID_C]; // fp16 gemm1/2 out (gather src)
// pre-converted weights, padded [KP][136] fp16 hi/lo
__device__ __align__(16) __half g_W1h[KP1 * 136];
__device__ __align__(16) __half g_W1l[KP1 * 136];
__device__ __align__(16) __half g_W2h[KP2 * 136];
__device__ __align__(16) __half g_W2l[KP2 * 136];
__device__ __align__(16) __half g_W3h[KP3 * 136];
__device__ __align__(16) __half g_W3l[KP3 * 136];

// ---------------- graph preprocessing -----------------------------------
__global__ void k_zero_cnt() {
    int i = blockIdx.x * blockDim.x + threadIdx.x;
    if (i < N_NODES) g_cnt[i] = 0;
}
__global__ void k_hist(const int* __restrict__ ei) {
    int e = blockIdx.x * blockDim.x + threadIdx.x;
    if (e < N_EDGES) atomicAdd(&g_cnt[ei[N_EDGES + e]], 1);
}
__global__ void k_scan1() {
    __shared__ int sw[8];
    int i = blockIdx.x * 256 + threadIdx.x;
    int v = (i < N_NODES) ? g_cnt[i] : 0;
    int lane = threadIdx.x & 31, wid = threadIdx.x >> 5;
    #pragma unroll
    for (int o = 16; o > 0; o >>= 1) v += __shfl_down_sync(0xffffffffu, v, o);
    if (lane == 0) sw[wid] = v;
    __syncthreads();
    if (wid == 0) {
        int s = (lane < 8) ? sw[lane] : 0;
        #pragma unroll
        for (int o = 4; o > 0; o >>= 1) s += __shfl_down_sync(0xffu, s, o);
        if (lane == 0) g_blksum[blockIdx.x] = s;
    }
}
__global__ void k_scan2(int nblk) {
    __shared__ int sw[8];
    int t = threadIdx.x, lane = t & 31, wid = t >> 5;
    int v = (t < nblk) ? g_blksum[t] : 0;
    int x = v;
    #pragma unroll
    for (int o = 1; o < 32; o <<= 1) { int y = __shfl_up_sync(0xffffffffu, x, o); if (lane >= o) x += y; }
    if (lane == 31) sw[wid] = x;
    __syncthreads();
    if (wid == 0 && lane < 8) {
        int wx = sw[lane];
        #pragma unroll
        for (int o = 1; o < 8; o <<= 1) { int y = __shfl_up_sync(0xffu, wx, o); if (lane >= o) wx += y; }
        sw[lane] = wx;
    }
    __syncthreads();
    int excl = x - v + (wid ? sw[wid - 1] : 0);
    if (t < nblk) g_blkoff[t] = excl;
}
__global__ void k_scan3() {   // also computes dinv
    __shared__ int sw[8];
    int i = blockIdx.x * 256 + threadIdx.x;
    int t = threadIdx.x, lane = t & 31, wid = t >> 5;
    int v = (i < N_NODES) ? g_cnt[i] : 0;
    int x = v;
    #pragma unroll
    for (int o = 1; o < 32; o <<= 1) { int y = __shfl_up_sync(0xffffffffu, x, o); if (lane >= o) x += y; }
    if (lane == 31) sw[wid] = x;
    __syncthreads();
    if (wid == 0 && lane < 8) {
        int wx = sw[lane];
        #pragma unroll
        for (int o = 1; o < 8; o <<= 1) { int y = __shfl_up_sync(0xffu, wx, o); if (lane >= o) wx += y; }
        sw[lane] = wx;
    }
    __syncthreads();
    int excl = x - v + (wid ? sw[wid - 1] : 0) + g_blkoff[blockIdx.x];
    if (i < N_NODES) {
        g_rowptr[i] = excl; g_cursor[i] = excl;
        g_dinv[i] = rsqrtf((float)v + 1.0f);
    }
    if (i == 0) g_rowptr[N_NODES] = N_EDGES;
}
__global__ void k_fill(const int* __restrict__ ei) {
    int e = blockIdx.x * blockDim.x + threadIdx.x;
    if (e < N_EDGES) {
        int s = ei[e];
        int d = ei[N_EDGES + e];
        int p = atomicAdd(&g_cursor[d], 1);
        g_srce[p] = s;
    }
}

// ---------------- weight prepass: fp32 W[K,Nact] -> fp16 hi/lo [KP][136] -----
__global__ void k_prepW(const float* __restrict__ W,
                        __half* __restrict__ oh, __half* __restrict__ ol,
                        int K, int Nact, int KP) {
    int i = blockIdx.x * 256 + threadIdx.x;
    if (i >= KP * 136) return;
    int k = i / 136, n = i - k * 136;
    float v = (k < K && n < Nact) ? W[(size_t)k * Nact + n] : 0.f;
    __half h = __float2half_rn(v);
    oh[i] = h;
    ol[i] = __float2half_rn(v - __half2float(h));
}

// ---------------- pipelined mma.sync fp16 GEMM (A single + B hi/lo, 2-term) --
#define A_ST 40
#define B_ST 136
#define OFF_BH 10240
#define OFF_BL 18944
#define STAGE_B 27648
#define GEMM_SMEM (2 * STAGE_B)

__device__ __forceinline__ uint32_t smem_u32(const void* p) {
    uint32_t a;
    asm("{ .reg .u64 t; cvta.to.shared.u64 t, %1; cvt.u32.u64 %0, t; }" : "=r"(a) : "l"(p));
    return a;
}
__device__ __forceinline__ void cpa16(uint32_t dst, const void* src) {
    asm volatile("cp.async.cg.shared.global [%0], [%1], 16;" :: "r"(dst), "l"(src));
}
#define CP_COMMIT() asm volatile("cp.async.commit_group;" ::: "memory")
#define CP_WAIT0()  asm volatile("cp.async.wait_group 0;" ::: "memory")

__device__ __forceinline__ void ldmx4(uint32_t* r, uint32_t addr) {
    asm volatile("ldmatrix.sync.aligned.m8n8.x4.shared.b16 {%0,%1,%2,%3}, [%4];"
        : "=r"(r[0]), "=r"(r[1]), "=r"(r[2]), "=r"(r[3]) : "r"(addr));
}
__device__ __forceinline__ void ldmx2t(uint32_t* r, uint32_t addr) {
    asm volatile("ldmatrix.sync.aligned.m8n8.x2.trans.shared.b16 {%0,%1}, [%2];"
        : "=r"(r[0]), "=r"(r[1]) : "r"(addr));
}
__device__ __forceinline__ void mma16816h(float* d, const uint32_t* a, const uint32_t* b) {
    asm volatile(
        "mma.sync.aligned.m16n8k16.row.col.f32.f16.f16.f32 "
        "{%0,%1,%2,%3}, {%4,%5,%6,%7}, {%8,%9}, {%0,%1,%2,%3};"
        : "+f"(d[0]), "+f"(d[1]), "+f"(d[2]), "+f"(d[3])
        : "r"(a[0]), "r"(a[1]), "r"(a[2]), "r"(a[3]), "r"(b[0]), "r"(b[1]));
}

// VEC4: A rows 16B-vectorizable (K%4==0). CHALF: C stored fp16 (Nact==128 only).
template<bool VEC4, bool CHALF>
__global__ __launch_bounds__(256, 2) void k_gemm_mma(
    const float* __restrict__ A,
    const __half* __restrict__ Wh, const __half* __restrict__ Wl,
    void* __restrict__ Cv, int M, int K, int Nact)
{
    extern __shared__ char smp[];
    const uint32_t sbase = smem_u32(smp);

    const int tid = threadIdx.x, lane = tid & 31, warp = tid >> 5;
    const int wm = warp >> 2, wn = warp & 3;           // 2 x 4 warp grid
    const int rowBase = blockIdx.x * 128;

    const int grp = lane >> 3;
    const uint32_t aLane = (uint32_t)((((grp & 1) * 8 + (lane & 7)) * A_ST + (grp >> 1) * 8) * 2);
    const uint32_t bLane = (uint32_t)(((lane & 15) * B_ST + wn * 32) * 2);

    float acc[4][4][4];
    #pragma unroll
    for (int i = 0; i < 4; i++)
        #pragma unroll
        for (int j = 0; j < 4; j++)
            #pragma unroll
            for (int r = 0; r < 4; r++) acc[i][j][r] = 0.f;

    const int NC = (K + 31) / 32;
    float aReg[16];

    auto copyB = [&](int c, uint32_t st) {
        const char* sH = (const char*)(Wh + (size_t)c * 32 * 136);
        const char* sL = (const char*)(Wl + (size_t)c * 32 * 136);
        uint32_t dH = st + OFF_BH, dL = st + OFF_BL;
        #pragma unroll
        for (int u = 0; u < 3; u++) {
            int i = u * 256 + tid;
            if (i < 544) {
                cpa16(dH + (uint32_t)i * 16, sH + i * 16);
                cpa16(dL + (uint32_t)i * 16, sL + i * 16);
            }
        }
    };
    auto loadA = [&](int c) {
        const int k0 = c * 32;
        if (VEC4) {
            #pragma unroll
            for (int u = 0; u < 4; u++) {
                int idx = u * 256 + tid;
                int kq = (idx & 7) * 4, m = idx >> 3;
                int gm = rowBase + m;
                float4 v = {0.f, 0.f, 0.f, 0.f};
                if (gm < M) v = *(const float4*)(A + (size_t)gm * K + k0 + kq);
                aReg[u * 4 + 0] = v.x; aReg[u * 4 + 1] = v.y;
                aReg[u * 4 + 2] = v.z; aReg[u * 4 + 3] = v.w;
            }
        } else {
            #pragma unroll
            for (int u = 0; u < 16; u++) {
                int m = u * 8 + warp;
                int gm = rowBase + m, gk = k0 + lane;
                aReg[u] = (gm < M && gk < K) ? __ldg(&A[(size_t)gm * K + gk]) : 0.f;
            }
        }
    };
    auto convA = [&](uint32_t st) {
        __half* ah = (__half*)(smp + (st - sbase));
        if (VEC4) {
            #pragma unroll
            for (int u = 0; u < 4; u++) {
                int idx = u * 256 + tid;
                int kq = (idx & 7) * 4, m = idx >> 3;
                __half2 h0 = __floats2half2_rn(aReg[u * 4 + 0], aReg[u * 4 + 1]);
                __half2 h1 = __floats2half2_rn(aReg[u * 4 + 2], aReg[u * 4 + 3]);
                uint2 pk = { *(uint32_t*)&h0, *(uint32_t*)&h1 };
                *(uint2*)&ah[m * A_ST + kq] = pk;
            }
        } else {
            #pragma unroll
            for (int u = 0; u < 16; u++) {
                int m = u * 8 + warp;
                ah[m * A_ST + lane] = __float2half_rn(aReg[u]);
            }
        }
    };

    copyB(0, sbase);
    CP_COMMIT();
    loadA(0);
    convA(sbase);
    CP_WAIT0();

    for (int c = 0; c < NC; c++) {
        __syncthreads();
        const uint32_t stN = sbase + (uint32_t)((c + 1) & 1) * STAGE_B;
        const bool more = (c + 1 < NC);
        if (more) { copyB(c + 1, stN); }
        CP_COMMIT();
        if (more) loadA(c + 1);

        const uint32_t st = sbase + (uint32_t)(c & 1) * STAGE_B;
        const uint32_t uAh = st, uBh = st + OFF_BH, uBl = st + OFF_BL;
        #pragma unroll
        for (int ks = 0; ks < 2; ks++) {
            uint32_t bh[4][2], bl[4][2];
            #pragma unroll
            for (int nt = 0; nt < 4; nt++) {
                uint32_t bo = (uint32_t)(ks * 16 * B_ST * 2) + bLane + (uint32_t)(nt * 16);
                ldmx2t(bh[nt], uBh + bo);
                ldmx2t(bl[nt], uBl + bo);
            }
            #pragma unroll
            for (int mt = 0; mt < 4; mt++) {
                uint32_t ao = aLane + (uint32_t)(((wm * 64 + mt * 16) * A_ST + ks * 16) * 2);
                uint32_t ah[4];
                ldmx4(ah, uAh + ao);
                #pragma unroll
                for (int nt = 0; nt < 4; nt++) mma16816h(acc[mt][nt], ah, bh[nt]);
                #pragma unroll
                for (int nt = 0; nt < 4; nt++) mma16816h(acc[mt][nt], ah, bl[nt]);
            }
        }

        if (more) convA(stN);
        CP_WAIT0();
    }

    // ---- store C ----
    const int r = lane >> 2, cc = (lane & 3) * 2;
    #pragma unroll
    for (int mt = 0; mt < 4; mt++) {
        int m0 = rowBase + wm * 64 + mt * 16 + r;
        #pragma unroll
        for (int nt = 0; nt < 4; nt++) {
            int n0 = wn * 32 + nt * 8 + cc;
            if (CHALF) {               // Nact == 128 guaranteed
                __half* C = (__half*)Cv;
                if (m0 < M)
                    *(__half2*)(C + (size_t)m0 * 128 + n0) = __floats2half2_rn(acc[mt][nt][0], acc[mt][nt][1]);
                if (m0 + 8 < M)
                    *(__half2*)(C + (size_t)(m0 + 8) * 128 + n0) = __floats2half2_rn(acc[mt][nt][2], acc[mt][nt][3]);
            } else if (Nact == 128) {
                float* C = (float*)Cv;
                if (m0 < M) {
                    float2 v = { acc[mt][nt][0], acc[mt][nt][1] };
                    *(float2*)(C + (size_t)m0 * 128 + n0) = v;
                }
                if (m0 + 8 < M) {
                    float2 v = { acc[mt][nt][2], acc[mt][nt][3] };
                    *(float2*)(C + (size_t)(m0 + 8) * 128 + n0) = v;
                }
            } else {
                float* C = (float*)Cv;
                if (m0 < M) {
                    if (n0 < Nact)     C[(size_t)m0 * Nact + n0]     = acc[mt][nt][0];
                    if (n0 + 1 < Nact) C[(size_t)m0 * Nact + n0 + 1] = acc[mt][nt][1];
                }
                if (m0 + 8 < M) {
                    if (n0 < Nact)     C[(size_t)(m0 + 8) * Nact + n0]     = acc[mt][nt][2];
                    if (n0 + 1 < Nact) C[(size_t)(m0 + 8) * Nact + n0 + 1] = acc[mt][nt][3];
                }
            }
        }
    }
}

// ---------------- aggregation (fp16 gather, fp32 accum/output) ----------------
template<bool RELU>
__global__ __launch_bounds__(128) void k_agg128h(const float* __restrict__ bias) {
    const __half* hw = g_bufH;          // row stride 128 halfs (256 B)
    float* out = g_bufB;
    __shared__ int   s_idx[4][32];
    __shared__ float s_wt [4][32];

    int w    = threadIdx.x >> 5;
    int lane = threadIdx.x & 31;
    int node = blockIdx.x * 4 + w;
    if (node >= N_NODES) return;

    int beg = g_rowptr[node];
    int end = g_rowptr[node + 1];
    float dd = g_dinv[node];

    float ax = 0.f, ay = 0.f, az = 0.f, aw = 0.f;

    for (int base = beg; base < end; base += 32) {
        int n = end - base; if (n > 32) n = 32;
        int si = 0; float swt = 0.f;
        if (lane < n) { si = g_srce[base + lane]; swt = g_dinv[si] * dd; }
        s_idx[w][lane] = si; s_wt[w][lane] = swt;
        __syncwarp();
        if (n == 32) {
            #pragma unroll 8
            for (int j = 0; j < 32; j++) {
                int ss = s_idx[w][j]; float ww = s_wt[w][j];
                uint2 raw = *(const uint2*)(hw + (size_t)ss * 128 + lane * 4);
                float2 f0 = __half22float2(*(__half2*)&raw.x);
                float2 f1 = __half22float2(*(__half2*)&raw.y);
                ax += f0.x * ww; ay += f0.y * ww; az += f1.x * ww; aw += f1.y * ww;
            }
        } else {
            for (int j = 0; j < n; j++) {
                int ss = s_idx[w][j]; float ww = s_wt[w][j];
                uint2 raw = *(const uint2*)(hw + (size_t)ss * 128 + lane * 4);
                float2 f0 = __half22float2(*(__half2*)&raw.x);
                float2 f1 = __half22float2(*(__half2*)&raw.y);
                ax += f0.x * ww; ay += f0.y * ww; az += f1.x * ww; aw += f1.y * ww;
            }
        }
        __syncwarp();
    }

    {   // self-loop
        float ww = dd * dd;
        uint2 raw = *(const uint2*)(hw + (size_t)node * 128 + lane * 4);
        float2 f0 = __half22float2(*(__half2*)&raw.x);
        float2 f1 = __half22float2(*(__half2*)&raw.y);
        ax += f0.x * ww; ay += f0.y * ww; az += f1.x * ww; aw += f1.y * ww;
    }
    float4 b = *(const float4*)(bias + lane * 4);
    ax += b.x; ay += b.y; az += b.z; aw += b.w;
    if (RELU) {
        ax = fmaxf(ax, 0.f); ay = fmaxf(ay, 0.f);
        az = fmaxf(az, 0.f); aw = fmaxf(aw, 0.f);
    }
    float4 rr = { ax, ay, az, aw };
    *(float4*)(out + (size_t)node * 128 + lane * 4) = rr;
}

__global__ __launch_bounds__(128) void k_agg47(const float* __restrict__ bias,
                                               float* __restrict__ out) {
    const float* hw = g_bufA;   // stride 47
    __shared__ int   s_idx[4][32];
    __shared__ float s_wt [4][32];

    int w    = threadIdx.x >> 5;
    int lane = threadIdx.x & 31;
    int node = blockIdx.x * 4 + w;
    if (node >= N_NODES) return;

    int beg = g_rowptr[node];
    int end = g_rowptr[node + 1];
    float dd = g_dinv[node];
    bool hi = (lane < OUT_C - 32);

    float a0 = 0.f, a1 = 0.f;

    for (int base = beg; base < end; base += 32) {
        int n = end - base; if (n > 32) n = 32;
        int si = 0; float swt = 0.f;
        if (lane < n) { si = g_srce[base + lane]; swt = g_dinv[si] * dd; }
        s_idx[w][lane] = si; s_wt[w][lane] = swt;
        __syncwarp();
        for (int j = 0; j < n; j++) {
            int ss = s_idx[w][j]; float ww = s_wt[w][j];
            const float* row = hw + (size_t)ss * OUT_C;
            a0 += row[lane] * ww;
            if (hi) a1 += row[lane + 32] * ww;
        }
        __syncwarp();
    }
    {
        float ww = dd * dd;
        const float* row = hw + (size_t)node * OUT_C;
        a0 += row[lane] * ww;
        if (hi) a1 += row[lane + 32] * ww;
    }
    a0 += bias[lane];
    if (hi) a1 += bias[lane + 32];

    out[(size_t)node * OUT_C + lane] = a0;
    if (hi) out[(size_t)node * OUT_C + lane + 32] = a1;
}

// ---------------- launch ------------------------------------------------
extern "C" void kernel_launch(void* const* d_in, const int* in_sizes, int n_in,
                              void* d_out, int out_size) {
    const float* x  = (const float*)d_in[0];
    const int*   ei = (const int*)  d_in[1];
    const float* W1 = (const float*)d_in[2];
    const float* b1 = (const float*)d_in[3];
    const float* W2 = (const float*)d_in[4];
    const float* b2 = (const float*)d_in[5];
    const float* W3 = (const float*)d_in[6];
    const float* b3 = (const float*)d_in[7];
    float* out = (float*)d_out;

    void *pA, *pB, *pH, *p1h, *p1l, *p2h, *p2l, *p3h, *p3l;
    cudaGetSymbolAddress(&pA, g_bufA);
    cudaGetSymbolAddress(&pB, g_bufB);
    cudaGetSymbolAddress(&pH, g_bufH);
    cudaGetSymbolAddress(&p1h, g_W1h); cudaGetSymbolAddress(&p1l, g_W1l);
    cudaGetSymbolAddress(&p2h, g_W2h); cudaGetSymbolAddress(&p2l, g_W2l);
    cudaGetSymbolAddress(&p3h, g_W3h); cudaGetSymbolAddress(&p3l, g_W3l);
    float* bufA = (float*)pA;
    float* bufB = (float*)pB;

    cudaFuncSetAttribute((const void*)&k_gemm_mma<false, true>, cudaFuncAttributeMaxDynamicSharedMemorySize, GEMM_SMEM);
    cudaFuncSetAttribute((const void*)&k_gemm_mma<true,  true>, cudaFuncAttributeMaxDynamicSharedMemorySize, GEMM_SMEM);
    cudaFuncSetAttribute((const void*)&k_gemm_mma<true, false>, cudaFuncAttributeMaxDynamicSharedMemorySize, GEMM_SMEM);

    const int NB = (N_NODES + 255) / 256;
    const int EB = (N_EDGES + 255) / 256;
    const int gemmGrid = (N_NODES + 127) / 128;  // 391
    const int aggGrid  = (N_NODES + 3) / 4;

    // launches 0-2
    k_zero_cnt<<<NB, 256>>>();
    k_hist<<<EB, 256>>>(ei);
    k_prepW<<<(KP1 * 136 + 255) / 256, 256>>>(W1, (__half*)p1h, (__half*)p1l, IN_C, HID_C, KP1);
    // launch 3: GEMM1 (profiled) -> fp16 C
    k_gemm_mma<false, true><<<gemmGrid, 256, GEMM_SMEM>>>(x, (const __half*)p1h, (const __half*)p1l,
                                                          pH, N_NODES, IN_C, HID_C);
    // CSR build
    k_scan1<<<NB, 256>>>();
    k_scan2<<<1, 256>>>(NB);
    k_scan3<<<NB, 256>>>();
    k_fill<<<EB, 256>>>(ei);
    k_prepW<<<(KP2 * 136 + 255) / 256, 256>>>(W2, (__half*)p2h, (__half*)p2l, HID_C, HID_C, KP2);
    k_prepW<<<(KP3 * 136 + 255) / 256, 256>>>(W3, (__half*)p3h, (__half*)p3l, HID_C, OUT_C, KP3);
    // layer 1 agg (fp16 gather -> fp32 h)
    k_agg128h<true><<<aggGrid, 128>>>(b1);
    // layer 2 -> fp16 C
    k_gemm_mma<true, true><<<gemmGrid, 256, GEMM_SMEM>>>(bufB, (const __half*)p2h, (const __half*)p2l,
                                                         pH, N_NODES, HID_C, HID_C);
    k_agg128h<true><<<aggGrid, 128>>>(b2);
    // layer 3 -> fp32 C (stride 47)
    k_gemm_mma<true, false><<<gemmGrid, 256, GEMM_SMEM>>>(bufB, (const __half*)p3h, (const __half*)p3l,
                                                          pA, N_NODES, HID_C, OUT_C);
    k_agg47<<<aggGrid, 128>>>(b3, out);
}

// round 9
// speedup vs baseline: 3.6095x; 1.0612x over previous
#include <cuda_runtime.h>
#include <cuda_bf16.h>
#include <cuda_fp16.h>
#include <cstdint>

#define N_NODES 50000
#define N_EDGES 1600000
#define IN_C    1433
#define HID_C   128
#define OUT_C   47

#define KP1 1440   // 45 chunks * 32
#define KP2 128
#define KP3 128

// ---------------- scratch (static device globals; no runtime alloc) ----------
__device__ int   g_cnt[N_NODES];
__device__ int   g_rowptr[N_NODES + 1];
__device__ int   g_cursor[N_NODES];
__device__ int   g_srce[N_EDGES];
__device__ float g_dinv[N_NODES];
__device__ int   g_blksum[256];
__device__ int   g_blkoff[256];
__device__ __align__(16) float  g_bufA[(size_t)N_NODES * HID_C]; // fp32 gemm3 out (stride 47)
__device__ __align__(16) float  g_bufB[(size_t)N_NODES * HID_C]; // fp32 agg out (gemm2/3 input)
__device__ __align__(16) __half g_bufH[(size_t)N_NODES * HID_C]; // fp16 gemm1/2 out (gather src)
// pre-converted weights, padded [KP][136] fp16
__device__ __align__(16) __half g_W1h[KP1 * 136];
__device__ __align__(16) __half g_W2h[KP2 * 136];
__device__ __align__(16) __half g_W3h[KP3 * 136];

// ---------------- graph preprocessing -----------------------------------
__global__ void k_zero_cnt() {
    int i = blockIdx.x * blockDim.x + threadIdx.x;
    if (i < N_NODES) g_cnt[i] = 0;
}
__global__ void k_hist(const int* __restrict__ ei) {
    int e = blockIdx.x * blockDim.x + threadIdx.x;
    if (e < N_EDGES) atomicAdd(&g_cnt[ei[N_EDGES + e]], 1);
}
__global__ void k_scan1() {
    __shared__ int sw[8];
    int i = blockIdx.x * 256 + threadIdx.x;
    int v = (i < N_NODES) ? g_cnt[i] : 0;
    int lane = threadIdx.x & 31, wid = threadIdx.x >> 5;
    #pragma unroll
    for (int o = 16; o > 0; o >>= 1) v += __shfl_down_sync(0xffffffffu, v, o);
    if (lane == 0) sw[wid] = v;
    __syncthreads();
    if (wid == 0) {
        int s = (lane < 8) ? sw[lane] : 0;
        #pragma unroll
        for (int o = 4; o > 0; o >>= 1) s += __shfl_down_sync(0xffu, s, o);
        if (lane == 0) g_blksum[blockIdx.x] = s;
    }
}
__global__ void k_scan2(int nblk) {
    __shared__ int sw[8];
    int t = threadIdx.x, lane = t & 31, wid = t >> 5;
    int v = (t < nblk) ? g_blksum[t] : 0;
    int x = v;
    #pragma unroll
    for (int o = 1; o < 32; o <<= 1) { int y = __shfl_up_sync(0xffffffffu, x, o); if (lane >= o) x += y; }
    if (lane == 31) sw[wid] = x;
    __syncthreads();
    if (wid == 0 && lane < 8) {
        int wx = sw[lane];
        #pragma unroll
        for (int o = 1; o < 8; o <<= 1) { int y = __shfl_up_sync(0xffu, wx, o); if (lane >= o) wx += y; }
        sw[lane] = wx;
    }
    __syncthreads();
    int excl = x - v + (wid ? sw[wid - 1] : 0);
    if (t < nblk) g_blkoff[t] = excl;
}
__global__ void k_scan3() {   // also computes dinv
    __shared__ int sw[8];
    int i = blockIdx.x * 256 + threadIdx.x;
    int t = threadIdx.x, lane = t & 31, wid = t >> 5;
    int v = (i < N_NODES) ? g_cnt[i] : 0;
    int x = v;
    #pragma unroll
    for (int o = 1; o < 32; o <<= 1) { int y = __shfl_up_sync(0xffffffffu, x, o); if (lane >= o) x += y; }
    if (lane == 31) sw[wid] = x;
    __syncthreads();
    if (wid == 0 && lane < 8) {
        int wx = sw[lane];
        #pragma unroll
        for (int o = 1; o < 8; o <<= 1) { int y = __shfl_up_sync(0xffu, wx, o); if (lane >= o) wx += y; }
        sw[lane] = wx;
    }
    __syncthreads();
    int excl = x - v + (wid ? sw[wid - 1] : 0) + g_blkoff[blockIdx.x];
    if (i < N_NODES) {
        g_rowptr[i] = excl; g_cursor[i] = excl;
        g_dinv[i] = rsqrtf((float)v + 1.0f);
    }
    if (i == 0) g_rowptr[N_NODES] = N_EDGES;
}
__global__ void k_fill(const int* __restrict__ ei) {
    int e = blockIdx.x * blockDim.x + threadIdx.x;
    if (e < N_EDGES) {
        int s = ei[e];
        int d = ei[N_EDGES + e];
        int p = atomicAdd(&g_cursor[d], 1);
        g_srce[p] = s;
    }
}

// ---------------- weight prepass: fp32 W[K,Nact] -> fp16 [KP][136] -----------
__global__ void k_prepW(const float* __restrict__ W,
                        __half* __restrict__ oh, int K, int Nact, int KP) {
    int i = blockIdx.x * 256 + threadIdx.x;
    if (i >= KP * 136) return;
    int k = i / 136, n = i - k * 136;
    float v = (k < K && n < Nact) ? W[(size_t)k * Nact + n] : 0.f;
    oh[i] = __float2half_rn(v);
}

// ---------------- pipelined mma.sync fp16 GEMM (1-term) ----------------------
#define A_ST 40
#define B_ST 136
#define OFF_BH 10240
#define STAGE_B 18944
#define GEMM_SMEM (2 * STAGE_B)

__device__ __forceinline__ uint32_t smem_u32(const void* p) {
    uint32_t a;
    asm("{ .reg .u64 t; cvta.to.shared.u64 t, %1; cvt.u32.u64 %0, t; }" : "=r"(a) : "l"(p));
    return a;
}
__device__ __forceinline__ void cpa16(uint32_t dst, const void* src) {
    asm volatile("cp.async.cg.shared.global [%0], [%1], 16;" :: "r"(dst), "l"(src));
}
#define CP_COMMIT() asm volatile("cp.async.commit_group;" ::: "memory")
#define CP_WAIT0()  asm volatile("cp.async.wait_group 0;" ::: "memory")

__device__ __forceinline__ void ldmx4(uint32_t* r, uint32_t addr) {
    asm volatile("ldmatrix.sync.aligned.m8n8.x4.shared.b16 {%0,%1,%2,%3}, [%4];"
        : "=r"(r[0]), "=r"(r[1]), "=r"(r[2]), "=r"(r[3]) : "r"(addr));
}
__device__ __forceinline__ void ldmx2t(uint32_t* r, uint32_t addr) {
    asm volatile("ldmatrix.sync.aligned.m8n8.x2.trans.shared.b16 {%0,%1}, [%2];"
        : "=r"(r[0]), "=r"(r[1]) : "r"(addr));
}
__device__ __forceinline__ void mma16816h(float* d, const uint32_t* a, const uint32_t* b) {
    asm volatile(
        "mma.sync.aligned.m16n8k16.row.col.f32.f16.f16.f32 "
        "{%0,%1,%2,%3}, {%4,%5,%6,%7}, {%8,%9}, {%0,%1,%2,%3};"
        : "+f"(d[0]), "+f"(d[1]), "+f"(d[2]), "+f"(d[3])
        : "r"(a[0]), "r"(a[1]), "r"(a[2]), "r"(a[3]), "r"(b[0]), "r"(b[1]));
}

// VEC4: A rows 16B-vectorizable (K%4==0). CHALF: C stored fp16 (Nact==128 only).
template<bool VEC4, bool CHALF>
__global__ __launch_bounds__(256, 2) void k_gemm_mma(
    const float* __restrict__ A,
    const __half* __restrict__ Wh,
    void* __restrict__ Cv, int M, int K, int Nact)
{
    extern __shared__ char smp[];
    const uint32_t sbase = smem_u32(smp);

    const int tid = threadIdx.x, lane = tid & 31, warp = tid >> 5;
    const int wm = warp >> 2, wn = warp & 3;           // 2 x 4 warp grid
    const int rowBase = blockIdx.x * 128;

    const int grp = lane >> 3;
    const uint32_t aLane = (uint32_t)((((grp & 1) * 8 + (lane & 7)) * A_ST + (grp >> 1) * 8) * 2);
    const uint32_t bLane = (uint32_t)(((lane & 15) * B_ST + wn * 32) * 2);

    float acc[4][4][4];
    #pragma unroll
    for (int i = 0; i < 4; i++)
        #pragma unroll
        for (int j = 0; j < 4; j++)
            #pragma unroll
            for (int r = 0; r < 4; r++) acc[i][j][r] = 0.f;

    const int NC = (K + 31) / 32;
    float aReg[16];

    auto copyB = [&](int c, uint32_t st) {
        const char* sH = (const char*)(Wh + (size_t)c * 32 * 136);
        uint32_t dH = st + OFF_BH;
        #pragma unroll
        for (int u = 0; u < 3; u++) {
            int i = u * 256 + tid;
            if (i < 544) cpa16(dH + (uint32_t)i * 16, sH + i * 16);
        }
    };
    auto loadA = [&](int c) {
        const int k0 = c * 32;
        if (VEC4) {
            #pragma unroll
            for (int u = 0; u < 4; u++) {
                int idx = u * 256 + tid;
                int kq = (idx & 7) * 4, m = idx >> 3;
                int gm = rowBase + m;
                float4 v = {0.f, 0.f, 0.f, 0.f};
                if (gm < M) v = *(const float4*)(A + (size_t)gm * K + k0 + kq);
                aReg[u * 4 + 0] = v.x; aReg[u * 4 + 1] = v.y;
                aReg[u * 4 + 2] = v.z; aReg[u * 4 + 3] = v.w;
            }
        } else {
            #pragma unroll
            for (int u = 0; u < 16; u++) {
                int m = u * 8 + warp;
                int gm = rowBase + m, gk = k0 + lane;
                aReg[u] = (gm < M && gk < K) ? __ldg(&A[(size_t)gm * K + gk]) : 0.f;
            }
        }
    };
    auto convA = [&](uint32_t st) {
        __half* ah = (__half*)(smp + (st - sbase));
        if (VEC4) {
            #pragma unroll
            for (int u = 0; u < 4; u++) {
                int idx = u * 256 + tid;
                int kq = (idx & 7) * 4, m = idx >> 3;
                __half2 h0 = __floats2half2_rn(aReg[u * 4 + 0], aReg[u * 4 + 1]);
                __half2 h1 = __floats2half2_rn(aReg[u * 4 + 2], aReg[u * 4 + 3]);
                uint2 pk = { *(uint32_t*)&h0, *(uint32_t*)&h1 };
                *(uint2*)&ah[m * A_ST + kq] = pk;
            }
        } else {
            #pragma unroll
            for (int u = 0; u < 16; u++) {
                int m = u * 8 + warp;
                ah[m * A_ST + lane] = __float2half_rn(aReg[u]);
            }
        }
    };

    copyB(0, sbase);
    CP_COMMIT();
    loadA(0);
    convA(sbase);
    CP_WAIT0();

    for (int c = 0; c < NC; c++) {
        __syncthreads();
        const uint32_t stN = sbase + (uint32_t)((c + 1) & 1) * STAGE_B;
        const bool more = (c + 1 < NC);
        if (more) { copyB(c + 1, stN); }
        CP_COMMIT();
        if (more) loadA(c + 1);

        const uint32_t st = sbase + (uint32_t)(c & 1) * STAGE_B;
        const uint32_t uAh = st, uBh = st + OFF_BH;
        #pragma unroll
        for (int ks = 0; ks < 2; ks++) {
            uint32_t bh[4][2];
            #pragma unroll
            for (int nt = 0; nt < 4; nt++) {
                uint32_t bo = (uint32_t)(ks * 16 * B_ST * 2) + bLane + (uint32_t)(nt * 16);
                ldmx2t(bh[nt], uBh + bo);
            }
            #pragma unroll
            for (int mt = 0; mt < 4; mt++) {
                uint32_t ao = aLane + (uint32_t)(((wm * 64 + mt * 16) * A_ST + ks * 16) * 2);
                uint32_t ah[4];
                ldmx4(ah, uAh + ao);
                #pragma unroll
                for (int nt = 0; nt < 4; nt++) mma16816h(acc[mt][nt], ah, bh[nt]);
            }
        }

        if (more) convA(stN);
        CP_WAIT0();
    }

    // ---- store C ----
    const int r = lane >> 2, cc = (lane & 3) * 2;
    #pragma unroll
    for (int mt = 0; mt < 4; mt++) {
        int m0 = rowBase + wm * 64 + mt * 16 + r;
        #pragma unroll
        for (int nt = 0; nt < 4; nt++) {
            int n0 = wn * 32 + nt * 8 + cc;
            if (CHALF) {               // Nact == 128 guaranteed
                __half* C = (__half*)Cv;
                if (m0 < M)
                    *(__half2*)(C + (size_t)m0 * 128 + n0) = __floats2half2_rn(acc[mt][nt][0], acc[mt][nt][1]);
                if (m0 + 8 < M)
                    *(__half2*)(C + (size_t)(m0 + 8) * 128 + n0) = __floats2half2_rn(acc[mt][nt][2], acc[mt][nt][3]);
            } else if (Nact == 128) {
                float* C = (float*)Cv;
                if (m0 < M) {
                    float2 v = { acc[mt][nt][0], acc[mt][nt][1] };
                    *(float2*)(C + (size_t)m0 * 128 + n0) = v;
                }
                if (m0 + 8 < M) {
                    float2 v = { acc[mt][nt][2], acc[mt][nt][3] };
                    *(float2*)(C + (size_t)(m0 + 8) * 128 + n0) = v;
                }
            } else {
                float* C = (float*)Cv;
                if (m0 < M) {
                    if (n0 < Nact)     C[(size_t)m0 * Nact + n0]     = acc[mt][nt][0];
                    if (n0 + 1 < Nact) C[(size_t)m0 * Nact + n0 + 1] = acc[mt][nt][1];
                }
                if (m0 + 8 < M) {
                    if (n0 < Nact)     C[(size_t)(m0 + 8) * Nact + n0]     = acc[mt][nt][2];
                    if (n0 + 1 < Nact) C[(size_t)(m0 + 8) * Nact + n0 + 1] = acc[mt][nt][3];
                }
            }
        }
    }
}

// ---------------- aggregation (fp16 gather, fp32 accum/output) ----------------
template<bool RELU>
__global__ __launch_bounds__(128) void k_agg128h(const float* __restrict__ bias) {
    const __half* hw = g_bufH;          // row stride 128 halfs (256 B)
    float* out = g_bufB;
    __shared__ int   s_idx[4][32];
    __shared__ float s_wt [4][32];

    int w    = threadIdx.x >> 5;
    int lane = threadIdx.x & 31;
    int node = blockIdx.x * 4 + w;
    if (node >= N_NODES) return;

    int beg = g_rowptr[node];
    int end = g_rowptr[node + 1];
    float dd = g_dinv[node];

    float ax = 0.f, ay = 0.f, az = 0.f, aw = 0.f;

    for (int base = beg; base < end; base += 32) {
        int n = end - base; if (n > 32) n = 32;
        int si = 0; float swt = 0.f;
        if (lane < n) { si = g_srce[base + lane]; swt = g_dinv[si] * dd; }
        s_idx[w][lane] = si; s_wt[w][lane] = swt;
        __syncwarp();
        if (n == 32) {
            #pragma unroll 8
            for (int j = 0; j < 32; j++) {
                int ss = s_idx[w][j]; float ww = s_wt[w][j];
                uint2 raw = *(const uint2*)(hw + (size_t)ss * 128 + lane * 4);
                float2 f0 = __half22float2(*(__half2*)&raw.x);
                float2 f1 = __half22float2(*(__half2*)&raw.y);
                ax += f0.x * ww; ay += f0.y * ww; az += f1.x * ww; aw += f1.y * ww;
            }
        } else {
            for (int j = 0; j < n; j++) {
                int ss = s_idx[w][j]; float ww = s_wt[w][j];
                uint2 raw = *(const uint2*)(hw + (size_t)ss * 128 + lane * 4);
                float2 f0 = __half22float2(*(__half2*)&raw.x);
                float2 f1 = __half22float2(*(__half2*)&raw.y);
                ax += f0.x * ww; ay += f0.y * ww; az += f1.x * ww; aw += f1.y * ww;
            }
        }
        __syncwarp();
    }

    {   // self-loop
        float ww = dd * dd;
        uint2 raw = *(const uint2*)(hw + (size_t)node * 128 + lane * 4);
        float2 f0 = __half22float2(*(__half2*)&raw.x);
        float2 f1 = __half22float2(*(__half2*)&raw.y);
        ax += f0.x * ww; ay += f0.y * ww; az += f1.x * ww; aw += f1.y * ww;
    }
    float4 b = *(const float4*)(bias + lane * 4);
    ax += b.x; ay += b.y; az += b.z; aw += b.w;
    if (RELU) {
        ax = fmaxf(ax, 0.f); ay = fmaxf(ay, 0.f);
        az = fmaxf(az, 0.f); aw = fmaxf(aw, 0.f);
    }
    float4 rr = { ax, ay, az, aw };
    *(float4*)(out + (size_t)node * 128 + lane * 4) = rr;
}

__global__ __launch_bounds__(128) void k_agg47(const float* __restrict__ bias,
                                               float* __restrict__ out) {
    const float* hw = g_bufA;   // stride 47
    __shared__ int   s_idx[4][32];
    __shared__ float s_wt [4][32];

    int w    = threadIdx.x >> 5;
    int lane = threadIdx.x & 31;
    int node = blockIdx.x * 4 + w;
    if (node >= N_NODES) return;

    int beg = g_rowptr[node];
    int end = g_rowptr[node + 1];
    float dd = g_dinv[node];
    bool hi = (lane < OUT_C - 32);

    float a0 = 0.f, a1 = 0.f;

    for (int base = beg; base < end; base += 32) {
        int n = end - base; if (n > 32) n = 32;
        int si = 0; float swt = 0.f;
        if (lane < n) { si = g_srce[base + lane]; swt = g_dinv[si] * dd; }
        s_idx[w][lane] = si; s_wt[w][lane] = swt;
        __syncwarp();
        for (int j = 0; j < n; j++) {
            int ss = s_idx[w][j]; float ww = s_wt[w][j];
            const float* row = hw + (size_t)ss * OUT_C;
            a0 += row[lane] * ww;
            if (hi) a1 += row[lane + 32] * ww;
        }
        __syncwarp();
    }
    {
        float ww = dd * dd;
        const float* row = hw + (size_t)node * OUT_C;
        a0 += row[lane] * ww;
        if (hi) a1 += row[lane + 32] * ww;
    }
    a0 += bias[lane];
    if (hi) a1 += bias[lane + 32];

    out[(size_t)node * OUT_C + lane] = a0;
    if (hi) out[(size_t)node * OUT_C + lane + 32] = a1;
}

// ---------------- launch ------------------------------------------------
extern "C" void kernel_launch(void* const* d_in, const int* in_sizes, int n_in,
                              void* d_out, int out_size) {
    const float* x  = (const float*)d_in[0];
    const int*   ei = (const int*)  d_in[1];
    const float* W1 = (const float*)d_in[2];
    const float* b1 = (const float*)d_in[3];
    const float* W2 = (const float*)d_in[4];
    const float* b2 = (const float*)d_in[5];
    const float* W3 = (const float*)d_in[6];
    const float* b3 = (const float*)d_in[7];
    float* out = (float*)d_out;

    void *pA, *pB, *pH, *p1h, *p2h, *p3h;
    cudaGetSymbolAddress(&pA, g_bufA);
    cudaGetSymbolAddress(&pB, g_bufB);
    cudaGetSymbolAddress(&pH, g_bufH);
    cudaGetSymbolAddress(&p1h, g_W1h);
    cudaGetSymbolAddress(&p2h, g_W2h);
    cudaGetSymbolAddress(&p3h, g_W3h);
    float* bufB = (float*)pB;

    cudaFuncSetAttribute((const void*)&k_gemm_mma<false, true>, cudaFuncAttributeMaxDynamicSharedMemorySize, GEMM_SMEM);
    cudaFuncSetAttribute((const void*)&k_gemm_mma<true,  true>, cudaFuncAttributeMaxDynamicSharedMemorySize, GEMM_SMEM);
    cudaFuncSetAttribute((const void*)&k_gemm_mma<true, false>, cudaFuncAttributeMaxDynamicSharedMemorySize, GEMM_SMEM);

    const int NB = (N_NODES + 255) / 256;
    const int EB = (N_EDGES + 255) / 256;
    const int gemmGrid = (N_NODES + 127) / 128;  // 391
    const int aggGrid  = (N_NODES + 3) / 4;

    // launches 0-2
    k_zero_cnt<<<NB, 256>>>();
    k_hist<<<EB, 256>>>(ei);
    k_prepW<<<(KP1 * 136 + 255) / 256, 256>>>(W1, (__half*)p1h, IN_C, HID_C, KP1);
    // launch 3: GEMM1 (profiled) -> fp16 C
    k_gemm_mma<false, true><<<gemmGrid, 256, GEMM_SMEM>>>(x, (const __half*)p1h,
                                                          pH, N_NODES, IN_C, HID_C);
    // CSR build
    k_scan1<<<NB, 256>>>();
    k_scan2<<<1, 256>>>(NB);
    k_scan3<<<NB, 256>>>();
    k_fill<<<EB, 256>>>(ei);
    k_prepW<<<(KP2 * 136 + 255) / 256, 256>>>(W2, (__half*)p2h, HID_C, HID_C, KP2);
    k_prepW<<<(KP3 * 136 + 255) / 256, 256>>>(W3, (__half*)p3h, HID_C, OUT_C, KP3);
    // layer 1 agg (fp16 gather -> fp32 h)
    k_agg128h<true><<<aggGrid, 128>>>(b1);
    // layer 2 -> fp16 C
    k_gemm_mma<true, true><<<gemmGrid, 256, GEMM_SMEM>>>(bufB, (const __half*)p2h,
                                                         pH, N_NODES, HID_C, HID_C);
    k_agg128h<true><<<aggGrid, 128>>>(b2);
    // layer 3 -> fp32 C (stride 47)
    k_gemm_mma<true, false><<<gemmGrid, 256, GEMM_SMEM>>>(bufB, (const __half*)p3h,
                                                          pA, N_NODES, HID_C, OUT_C);
    k_agg47<<<aggGrid, 128>>>(b3, out);
}

// round 10
// speedup vs baseline: 3.9636x; 1.0981x over previous
#include <cuda_runtime.h>
#include <cuda_bf16.h>
#include <cuda_fp16.h>
#include <cstdint>

#define N_NODES 50000
#define N_EDGES 1600000
#define IN_C    1433
#define HID_C   128
#define OUT_C   47

#define KP1 1440   // 45 chunks * 32
#define KP2 128
#define KP3 128

// ---------------- scratch (static device globals; no runtime alloc) ----------
__device__ int   g_cnt[N_NODES];
__device__ int   g_rowptr[N_NODES + 1];
__device__ int   g_cursor[N_NODES];
__device__ int   g_srce[N_EDGES];
__device__ float g_dinv[N_NODES];
__device__ int   g_blksum[256];
__device__ int   g_blkoff[256];
__device__ __align__(16) float  g_bufA[(size_t)N_NODES * HID_C]; // fp32 gemm3 out (stride 47)
__device__ __align__(16) float  g_bufB[(size_t)N_NODES * HID_C]; // fp32 agg out (gemm2/3 input)
__device__ __align__(16) __half g_bufH[(size_t)N_NODES * HID_C]; // fp16 gemm1/2 out (gather src)
// pre-converted weights, padded [KP][136] fp16
__device__ __align__(16) __half g_W1h[KP1 * 136];
__device__ __align__(16) __half g_W2h[KP2 * 136];
__device__ __align__(16) __half g_W3h[KP3 * 136];

// ---------------- graph preprocessing -----------------------------------
__global__ void k_zero_cnt() {
    int i = blockIdx.x * blockDim.x + threadIdx.x;
    if (i < N_NODES) g_cnt[i] = 0;
}
__global__ void k_hist(const int* __restrict__ ei) {
    int e = blockIdx.x * blockDim.x + threadIdx.x;
    if (e < N_EDGES) atomicAdd(&g_cnt[ei[N_EDGES + e]], 1);
}
__global__ void k_scan1() {
    __shared__ int sw[8];
    int i = blockIdx.x * 256 + threadIdx.x;
    int v = (i < N_NODES) ? g_cnt[i] : 0;
    int lane = threadIdx.x & 31, wid = threadIdx.x >> 5;
    #pragma unroll
    for (int o = 16; o > 0; o >>= 1) v += __shfl_down_sync(0xffffffffu, v, o);
    if (lane == 0) sw[wid] = v;
    __syncthreads();
    if (wid == 0) {
        int s = (lane < 8) ? sw[lane] : 0;
        #pragma unroll
        for (int o = 4; o > 0; o >>= 1) s += __shfl_down_sync(0xffu, s, o);
        if (lane == 0) g_blksum[blockIdx.x] = s;
    }
}
__global__ void k_scan2(int nblk) {
    __shared__ int sw[8];
    int t = threadIdx.x, lane = t & 31, wid = t >> 5;
    int v = (t < nblk) ? g_blksum[t] : 0;
    int x = v;
    #pragma unroll
    for (int o = 1; o < 32; o <<= 1) { int y = __shfl_up_sync(0xffffffffu, x, o); if (lane >= o) x += y; }
    if (lane == 31) sw[wid] = x;
    __syncthreads();
    if (wid == 0 && lane < 8) {
        int wx = sw[lane];
        #pragma unroll
        for (int o = 1; o < 8; o <<= 1) { int y = __shfl_up_sync(0xffu, wx, o); if (lane >= o) wx += y; }
        sw[lane] = wx;
    }
    __syncthreads();
    int excl = x - v + (wid ? sw[wid - 1] : 0);
    if (t < nblk) g_blkoff[t] = excl;
}
__global__ void k_scan3() {   // also computes dinv
    __shared__ int sw[8];
    int i = blockIdx.x * 256 + threadIdx.x;
    int t = threadIdx.x, lane = t & 31, wid = t >> 5;
    int v = (i < N_NODES) ? g_cnt[i] : 0;
    int x = v;
    #pragma unroll
    for (int o = 1; o < 32; o <<= 1) { int y = __shfl_up_sync(0xffffffffu, x, o); if (lane >= o) x += y; }
    if (lane == 31) sw[wid] = x;
    __syncthreads();
    if (wid == 0 && lane < 8) {
        int wx = sw[lane];
        #pragma unroll
        for (int o = 1; o < 8; o <<= 1) { int y = __shfl_up_sync(0xffu, wx, o); if (lane >= o) wx += y; }
        sw[lane] = wx;
    }
    __syncthreads();
    int excl = x - v + (wid ? sw[wid - 1] : 0) + g_blkoff[blockIdx.x];
    if (i < N_NODES) {
        g_rowptr[i] = excl; g_cursor[i] = excl;
        g_dinv[i] = rsqrtf((float)v + 1.0f);
    }
    if (i == 0) g_rowptr[N_NODES] = N_EDGES;
}
__global__ void k_fill(const int* __restrict__ ei) {
    int e = blockIdx.x * blockDim.x + threadIdx.x;
    if (e < N_EDGES) {
        int s = ei[e];
        int d = ei[N_EDGES + e];
        int p = atomicAdd(&g_cursor[d], 1);
        g_srce[p] = s;
    }
}

// ---------------- weight prepass: fp32 W[K,Nact] -> fp16 [KP][136] -----------
__global__ void k_prepW(const float* __restrict__ W,
                        __half* __restrict__ oh, int K, int Nact, int KP) {
    int i = blockIdx.x * 256 + threadIdx.x;
    if (i >= KP * 136) return;
    int k = i / 136, n = i - k * 136;
    float v = (k < K && n < Nact) ? W[(size_t)k * Nact + n] : 0.f;
    oh[i] = __float2half_rn(v);
}

// ---------------- pipelined mma.sync fp16 GEMM (1-term), 64x128 tile ---------
#define A_ST 40
#define B_ST 136
#define OFF_BH 5120            // A: 64*40*2 = 5120 B
#define STAGE_B 13824          // + B: 32*136*2 = 8704 B
#define GEMM_SMEM (2 * STAGE_B)

__device__ __forceinline__ uint32_t smem_u32(const void* p) {
    uint32_t a;
    asm("{ .reg .u64 t; cvta.to.shared.u64 t, %1; cvt.u32.u64 %0, t; }" : "=r"(a) : "l"(p));
    return a;
}
__device__ __forceinline__ void cpa16(uint32_t dst, const void* src) {
    asm volatile("cp.async.cg.shared.global [%0], [%1], 16;" :: "r"(dst), "l"(src));
}
#define CP_COMMIT() asm volatile("cp.async.commit_group;" ::: "memory")
#define CP_WAIT0()  asm volatile("cp.async.wait_group 0;" ::: "memory")

__device__ __forceinline__ void ldmx4(uint32_t* r, uint32_t addr) {
    asm volatile("ldmatrix.sync.aligned.m8n8.x4.shared.b16 {%0,%1,%2,%3}, [%4];"
        : "=r"(r[0]), "=r"(r[1]), "=r"(r[2]), "=r"(r[3]) : "r"(addr));
}
__device__ __forceinline__ void ldmx2t(uint32_t* r, uint32_t addr) {
    asm volatile("ldmatrix.sync.aligned.m8n8.x2.trans.shared.b16 {%0,%1}, [%2];"
        : "=r"(r[0]), "=r"(r[1]) : "r"(addr));
}
__device__ __forceinline__ void mma16816h(float* d, const uint32_t* a, const uint32_t* b) {
    asm volatile(
        "mma.sync.aligned.m16n8k16.row.col.f32.f16.f16.f32 "
        "{%0,%1,%2,%3}, {%4,%5,%6,%7}, {%8,%9}, {%0,%1,%2,%3};"
        : "+f"(d[0]), "+f"(d[1]), "+f"(d[2]), "+f"(d[3])
        : "r"(a[0]), "r"(a[1]), "r"(a[2]), "r"(a[3]), "r"(b[0]), "r"(b[1]));
}

// 64x128 CTA tile, 8 warps in 2x4 grid, warp tile 32x32 (mt 2 x nt 4).
template<bool VEC4, bool CHALF>
__global__ __launch_bounds__(256, 3) void k_gemm_mma(
    const float* __restrict__ A,
    const __half* __restrict__ Wh,
    void* __restrict__ Cv, int M, int K, int Nact)
{
    extern __shared__ char smp[];
    const uint32_t sbase = smem_u32(smp);

    const int tid = threadIdx.x, lane = tid & 31, warp = tid >> 5;
    const int wm = warp >> 2, wn = warp & 3;           // 2 x 4 warp grid
    const int rowBase = blockIdx.x * 64;

    const int grp = lane >> 3;
    const uint32_t aLane = (uint32_t)((((grp & 1) * 8 + (lane & 7)) * A_ST + (grp >> 1) * 8) * 2);
    const uint32_t bLane = (uint32_t)(((lane & 15) * B_ST + wn * 32) * 2);

    float acc[2][4][4];
    #pragma unroll
    for (int i = 0; i < 2; i++)
        #pragma unroll
        for (int j = 0; j < 4; j++)
            #pragma unroll
            for (int r = 0; r < 4; r++) acc[i][j][r] = 0.f;

    const int NC = (K + 31) / 32;
    float aReg[8];

    auto copyB = [&](int c, uint32_t st) {
        const char* sH = (const char*)(Wh + (size_t)c * 32 * 136);
        uint32_t dH = st + OFF_BH;
        #pragma unroll
        for (int u = 0; u < 3; u++) {
            int i = u * 256 + tid;
            if (i < 544) cpa16(dH + (uint32_t)i * 16, sH + i * 16);
        }
    };
    auto loadA = [&](int c) {
        const int k0 = c * 32;
        if (VEC4) {
            #pragma unroll
            for (int u = 0; u < 2; u++) {
                int idx = u * 256 + tid;           // 0..511 float4 slots
                int kq = (idx & 7) * 4, m = idx >> 3;
                int gm = rowBase + m;
                float4 v = {0.f, 0.f, 0.f, 0.f};
                if (gm < M) v = *(const float4*)(A + (size_t)gm * K + k0 + kq);
                aReg[u * 4 + 0] = v.x; aReg[u * 4 + 1] = v.y;
                aReg[u * 4 + 2] = v.z; aReg[u * 4 + 3] = v.w;
            }
        } else {
            #pragma unroll
            for (int u = 0; u < 8; u++) {
                int m = u * 8 + warp;
                int gm = rowBase + m, gk = k0 + lane;
                aReg[u] = (gm < M && gk < K) ? __ldg(&A[(size_t)gm * K + gk]) : 0.f;
            }
        }
    };
    auto convA = [&](uint32_t st) {
        __half* ah = (__half*)(smp + (st - sbase));
        if (VEC4) {
            #pragma unroll
            for (int u = 0; u < 2; u++) {
                int idx = u * 256 + tid;
                int kq = (idx & 7) * 4, m = idx >> 3;
                __half2 h0 = __floats2half2_rn(aReg[u * 4 + 0], aReg[u * 4 + 1]);
                __half2 h1 = __floats2half2_rn(aReg[u * 4 + 2], aReg[u * 4 + 3]);
                uint2 pk = { *(uint32_t*)&h0, *(uint32_t*)&h1 };
                *(uint2*)&ah[m * A_ST + kq] = pk;
            }
        } else {
            #pragma unroll
            for (int u = 0; u < 8; u++) {
                int m = u * 8 + warp;
                ah[m * A_ST + lane] = __float2half_rn(aReg[u]);
            }
        }
    };

    copyB(0, sbase);
    CP_COMMIT();
    loadA(0);
    convA(sbase);
    CP_WAIT0();

    for (int c = 0; c < NC; c++) {
        __syncthreads();
        const uint32_t stN = sbase + (uint32_t)((c + 1) & 1) * STAGE_B;
        const bool more = (c + 1 < NC);
        if (more) { copyB(c + 1, stN); }
        CP_COMMIT();
        if (more) loadA(c + 1);

        const uint32_t st = sbase + (uint32_t)(c & 1) * STAGE_B;
        const uint32_t uAh = st, uBh = st + OFF_BH;
        #pragma unroll
        for (int ks = 0; ks < 2; ks++) {
            uint32_t bh[4][2];
            #pragma unroll
            for (int nt = 0; nt < 4; nt++) {
                uint32_t bo = (uint32_t)(ks * 16 * B_ST * 2) + bLane + (uint32_t)(nt * 16);
                ldmx2t(bh[nt], uBh + bo);
            }
            #pragma unroll
            for (int mt = 0; mt < 2; mt++) {
                uint32_t ao = aLane + (uint32_t)(((wm * 32 + mt * 16) * A_ST + ks * 16) * 2);
                uint32_t ah[4];
                ldmx4(ah, uAh + ao);
                #pragma unroll
                for (int nt = 0; nt < 4; nt++) mma16816h(acc[mt][nt], ah, bh[nt]);
            }
        }

        if (more) convA(stN);
        CP_WAIT0();
    }

    // ---- store C ----
    const int r = lane >> 2, cc = (lane & 3) * 2;
    #pragma unroll
    for (int mt = 0; mt < 2; mt++) {
        int m0 = rowBase + wm * 32 + mt * 16 + r;
        #pragma unroll
        for (int nt = 0; nt < 4; nt++) {
            int n0 = wn * 32 + nt * 8 + cc;
            if (CHALF) {               // Nact == 128 guaranteed
                __half* C = (__half*)Cv;
                if (m0 < M)
                    *(__half2*)(C + (size_t)m0 * 128 + n0) = __floats2half2_rn(acc[mt][nt][0], acc[mt][nt][1]);
                if (m0 + 8 < M)
                    *(__half2*)(C + (size_t)(m0 + 8) * 128 + n0) = __floats2half2_rn(acc[mt][nt][2], acc[mt][nt][3]);
            } else if (Nact == 128) {
                float* C = (float*)Cv;
                if (m0 < M) {
                    float2 v = { acc[mt][nt][0], acc[mt][nt][1] };
                    *(float2*)(C + (size_t)m0 * 128 + n0) = v;
                }
                if (m0 + 8 < M) {
                    float2 v = { acc[mt][nt][2], acc[mt][nt][3] };
                    *(float2*)(C + (size_t)(m0 + 8) * 128 + n0) = v;
                }
            } else {
                float* C = (float*)Cv;
                if (m0 < M) {
                    if (n0 < Nact)     C[(size_t)m0 * Nact + n0]     = acc[mt][nt][0];
                    if (n0 + 1 < Nact) C[(size_t)m0 * Nact + n0 + 1] = acc[mt][nt][1];
                }
                if (m0 + 8 < M) {
                    if (n0 < Nact)     C[(size_t)(m0 + 8) * Nact + n0]     = acc[mt][nt][2];
                    if (n0 + 1 < Nact) C[(size_t)(m0 + 8) * Nact + n0 + 1] = acc[mt][nt][3];
                }
            }
        }
    }
}

// ---------------- aggregation (fp16 gather, fp32 accum/output) ----------------
template<bool RELU>
__global__ __launch_bounds__(128) void k_agg128h(const float* __restrict__ bias) {
    const __half* hw = g_bufH;          // row stride 128 halfs (256 B)
    float* out = g_bufB;
    __shared__ int   s_idx[4][32];
    __shared__ float s_wt [4][32];

    int w    = threadIdx.x >> 5;
    int lane = threadIdx.x & 31;
    int node = blockIdx.x * 4 + w;
    if (node >= N_NODES) return;

    int beg = g_rowptr[node];
    int end = g_rowptr[node + 1];
    float dd = g_dinv[node];

    float ax = 0.f, ay = 0.f, az = 0.f, aw = 0.f;

    for (int base = beg; base < end; base += 32) {
        int n = end - base; if (n > 32) n = 32;
        int si = 0; float swt = 0.f;
        if (lane < n) { si = g_srce[base + lane]; swt = g_dinv[si] * dd; }
        s_idx[w][lane] = si; s_wt[w][lane] = swt;
        __syncwarp();
        if (n == 32) {
            #pragma unroll 8
            for (int j = 0; j < 32; j++) {
                int ss = s_idx[w][j]; float ww = s_wt[w][j];
                uint2 raw = *(const uint2*)(hw + (size_t)ss * 128 + lane * 4);
                float2 f0 = __half22float2(*(__half2*)&raw.x);
                float2 f1 = __half22float2(*(__half2*)&raw.y);
                ax += f0.x * ww; ay += f0.y * ww; az += f1.x * ww; aw += f1.y * ww;
            }
        } else {
            for (int j = 0; j < n; j++) {
                int ss = s_idx[w][j]; float ww = s_wt[w][j];
                uint2 raw = *(const uint2*)(hw + (size_t)ss * 128 + lane * 4);
                float2 f0 = __half22float2(*(__half2*)&raw.x);
                float2 f1 = __half22float2(*(__half2*)&raw.y);
                ax += f0.x * ww; ay += f0.y * ww; az += f1.x * ww; aw += f1.y * ww;
            }
        }
        __syncwarp();
    }

    {   // self-loop
        float ww = dd * dd;
        uint2 raw = *(const uint2*)(hw + (size_t)node * 128 + lane * 4);
        float2 f0 = __half22float2(*(__half2*)&raw.x);
        float2 f1 = __half22float2(*(__half2*)&raw.y);
        ax += f0.x * ww; ay += f0.y * ww; az += f1.x * ww; aw += f1.y * ww;
    }
    float4 b = *(const float4*)(bias + lane * 4);
    ax += b.x; ay += b.y; az += b.z; aw += b.w;
    if (RELU) {
        ax = fmaxf(ax, 0.f); ay = fmaxf(ay, 0.f);
        az = fmaxf(az, 0.f); aw = fmaxf(aw, 0.f);
    }
    float4 rr = { ax, ay, az, aw };
    *(float4*)(out + (size_t)node * 128 + lane * 4) = rr;
}

__global__ __launch_bounds__(128) void k_agg47(const float* __restrict__ bias,
                                               float* __restrict__ out) {
    const float* hw = g_bufA;   // stride 47
    __shared__ int   s_idx[4][32];
    __shared__ float s_wt [4][32];

    int w    = threadIdx.x >> 5;
    int lane = threadIdx.x & 31;
    int node = blockIdx.x * 4 + w;
    if (node >= N_NODES) return;

    int beg = g_rowptr[node];
    int end = g_rowptr[node + 1];
    float dd = g_dinv[node];
    bool hi = (lane < OUT_C - 32);

    float a0 = 0.f, a1 = 0.f;

    for (int base = beg; base < end; base += 32) {
        int n = end - base; if (n > 32) n = 32;
        int si = 0; float swt = 0.f;
        if (lane < n) { si = g_srce[base + lane]; swt = g_dinv[si] * dd; }
        s_idx[w][lane] = si; s_wt[w][lane] = swt;
        __syncwarp();
        for (int j = 0; j < n; j++) {
            int ss = s_idx[w][j]; float ww = s_wt[w][j];
            const float* row = hw + (size_t)ss * OUT_C;
            a0 += row[lane] * ww;
            if (hi) a1 += row[lane + 32] * ww;
        }
        __syncwarp();
    }
    {
        float ww = dd * dd;
        const float* row = hw + (size_t)node * OUT_C;
        a0 += row[lane] * ww;
        if (hi) a1 += row[lane + 32] * ww;
    }
    a0 += bias[lane];
    if (hi) a1 += bias[lane + 32];

    out[(size_t)node * OUT_C + lane] = a0;
    if (hi) out[(size_t)node * OUT_C + lane + 32] = a1;
}

// ---------------- launch ------------------------------------------------
extern "C" void kernel_launch(void* const* d_in, const int* in_sizes, int n_in,
                              void* d_out, int out_size) {
    const float* x  = (const float*)d_in[0];
    const int*   ei = (const int*)  d_in[1];
    const float* W1 = (const float*)d_in[2];
    const float* b1 = (const float*)d_in[3];
    const float* W2 = (const float*)d_in[4];
    const float* b2 = (const float*)d_in[5];
    const float* W3 = (const float*)d_in[6];
    const float* b3 = (const float*)d_in[7];
    float* out = (float*)d_out;

    void *pA, *pB, *pH, *p1h, *p2h, *p3h;
    cudaGetSymbolAddress(&pA, g_bufA);
    cudaGetSymbolAddress(&pB, g_bufB);
    cudaGetSymbolAddress(&pH, g_bufH);
    cudaGetSymbolAddress(&p1h, g_W1h);
    cudaGetSymbolAddress(&p2h, g_W2h);
    cudaGetSymbolAddress(&p3h, g_W3h);
    float* bufB = (float*)pB;

    cudaFuncSetAttribute((const void*)&k_gemm_mma<false, true>, cudaFuncAttributeMaxDynamicSharedMemorySize, GEMM_SMEM);
    cudaFuncSetAttribute((const void*)&k_gemm_mma<true,  true>, cudaFuncAttributeMaxDynamicSharedMemorySize, GEMM_SMEM);
    cudaFuncSetAttribute((const void*)&k_gemm_mma<true, false>, cudaFuncAttributeMaxDynamicSharedMemorySize, GEMM_SMEM);

    // one-time side stream + events (resources only; identical launches per call)
    static cudaStream_t s2 = nullptr;
    static cudaEvent_t evFork = nullptr, evSide = nullptr;
    if (!s2) {
        cudaStreamCreateWithFlags(&s2, cudaStreamNonBlocking);
        cudaEventCreateWithFlags(&evFork, cudaEventDisableTiming);
        cudaEventCreateWithFlags(&evSide, cudaEventDisableTiming);
    }

    const int NB = (N_NODES + 255) / 256;
    const int EB = (N_EDGES + 255) / 256;
    const int gemmGrid = (N_NODES + 63) / 64;    // 782
    const int aggGrid  = (N_NODES + 3) / 4;

    // main stream: zero(0), hist(1), prepW1(2), gemm1(3)
    k_zero_cnt<<<NB, 256>>>();
    k_hist<<<EB, 256>>>(ei);
    cudaEventRecord(evFork, 0);
    k_prepW<<<(KP1 * 136 + 255) / 256, 256>>>(W1, (__half*)p1h, IN_C, HID_C, KP1);
    k_gemm_mma<false, true><<<gemmGrid, 256, GEMM_SMEM>>>(x, (const __half*)p1h,
                                                          pH, N_NODES, IN_C, HID_C);

    // side stream: CSR build + remaining weight prep, overlapped with GEMM1
    cudaStreamWaitEvent(s2, evFork, 0);
    k_scan1<<<NB, 256, 0, s2>>>();
    k_scan2<<<1, 256, 0, s2>>>(NB);
    k_scan3<<<NB, 256, 0, s2>>>();
    k_fill<<<EB, 256, 0, s2>>>(ei);
    k_prepW<<<(KP2 * 136 + 255) / 256, 256, 0, s2>>>(W2, (__half*)p2h, HID_C, HID_C, KP2);
    k_prepW<<<(KP3 * 136 + 255) / 256, 256, 0, s2>>>(W3, (__half*)p3h, HID_C, OUT_C, KP3);
    cudaEventRecord(evSide, s2);

    // join, then rest of the network on the main stream
    cudaStreamWaitEvent(0, evSide, 0);
    k_agg128h<true><<<aggGrid, 128>>>(b1);
    k_gemm_mma<true, true><<<gemmGrid, 256, GEMM_SMEM>>>(bufB, (const __half*)p2h,
                                                         pH, N_NODES, HID_C, HID_C);
    k_agg128h<true><<<aggGrid, 128>>>(b2);
    k_gemm_mma<true, false><<<gemmGrid, 256, GEMM_SMEM>>>(bufB, (const __half*)p3h,
                                                          pA, N_NODES, HID_C, OUT_C);
    k_agg47<<<aggGrid, 128>>>(b3, out);
}

// round 11
// speedup vs baseline: 3.9833x; 1.0050x over previous
#include <cuda_runtime.h>
#include <cuda_bf16.h>
#include <cuda_fp16.h>
#include <cstdint>

#define N_NODES 50000
#define N_EDGES 1600000
#define IN_C    1433
#define HID_C   128
#define OUT_C   47

#define KP1 1440   // 45 chunks * 32
#define KP2 128
#define KP3 128

// ---------------- scratch (static device globals; no runtime alloc) ----------
__device__ int   g_cnt[N_NODES];
__device__ int   g_rowptr[N_NODES + 1];
__device__ int   g_cursor[N_NODES];
__device__ int   g_srce[N_EDGES];
__device__ float g_dinv[N_NODES];
__device__ int   g_blksum[256];
__device__ int   g_blkoff[256];
__device__ __align__(16) __half g_bufH [(size_t)N_NODES * HID_C]; // gemm1/2 out (gather src), stride 128
__device__ __align__(16) __half g_bufHB[(size_t)N_NODES * HID_C]; // agg out h (gemm2/3 A), stride 128
__device__ __align__(16) __half g_buf48[(size_t)N_NODES * 48];    // gemm3 out, stride 48
// pre-converted weights, padded [KP][136] fp16
__device__ __align__(16) __half g_W1h[KP1 * 136];
__device__ __align__(16) __half g_W2h[KP2 * 136];
__device__ __align__(16) __half g_W3h[KP3 * 136];

// ---------------- graph preprocessing -----------------------------------
__global__ void k_zero_cnt() {
    int i = blockIdx.x * blockDim.x + threadIdx.x;
    if (i < N_NODES) g_cnt[i] = 0;
}
__global__ void k_hist(const int* __restrict__ ei) {
    int e = blockIdx.x * blockDim.x + threadIdx.x;
    if (e < N_EDGES) atomicAdd(&g_cnt[ei[N_EDGES + e]], 1);
}
__global__ void k_scan1() {
    __shared__ int sw[8];
    int i = blockIdx.x * 256 + threadIdx.x;
    int v = (i < N_NODES) ? g_cnt[i] : 0;
    int lane = threadIdx.x & 31, wid = threadIdx.x >> 5;
    #pragma unroll
    for (int o = 16; o > 0; o >>= 1) v += __shfl_down_sync(0xffffffffu, v, o);
    if (lane == 0) sw[wid] = v;
    __syncthreads();
    if (wid == 0) {
        int s = (lane < 8) ? sw[lane] : 0;
        #pragma unroll
        for (int o = 4; o > 0; o >>= 1) s += __shfl_down_sync(0xffu, s, o);
        if (lane == 0) g_blksum[blockIdx.x] = s;
    }
}
__global__ void k_scan2(int nblk) {
    __shared__ int sw[8];
    int t = threadIdx.x, lane = t & 31, wid = t >> 5;
    int v = (t < nblk) ? g_blksum[t] : 0;
    int x = v;
    #pragma unroll
    for (int o = 1; o < 32; o <<= 1) { int y = __shfl_up_sync(0xffffffffu, x, o); if (lane >= o) x += y; }
    if (lane == 31) sw[wid] = x;
    __syncthreads();
    if (wid == 0 && lane < 8) {
        int wx = sw[lane];
        #pragma unroll
        for (int o = 1; o < 8; o <<= 1) { int y = __shfl_up_sync(0xffu, wx, o); if (lane >= o) wx += y; }
        sw[lane] = wx;
    }
    __syncthreads();
    int excl = x - v + (wid ? sw[wid - 1] : 0);
    if (t < nblk) g_blkoff[t] = excl;
}
__global__ void k_scan3() {   // also computes dinv
    __shared__ int sw[8];
    int i = blockIdx.x * 256 + threadIdx.x;
    int t = threadIdx.x, lane = t & 31, wid = t >> 5;
    int v = (i < N_NODES) ? g_cnt[i] : 0;
    int x = v;
    #pragma unroll
    for (int o = 1; o < 32; o <<= 1) { int y = __shfl_up_sync(0xffffffffu, x, o); if (lane >= o) x += y; }
    if (lane == 31) sw[wid] = x;
    __syncthreads();
    if (wid == 0 && lane < 8) {
        int wx = sw[lane];
        #pragma unroll
        for (int o = 1; o < 8; o <<= 1) { int y = __shfl_up_sync(0xffu, wx, o); if (lane >= o) wx += y; }
        sw[lane] = wx;
    }
    __syncthreads();
    int excl = x - v + (wid ? sw[wid - 1] : 0) + g_blkoff[blockIdx.x];
    if (i < N_NODES) {
        g_rowptr[i] = excl; g_cursor[i] = excl;
        g_dinv[i] = rsqrtf((float)v + 1.0f);
    }
    if (i == 0) g_rowptr[N_NODES] = N_EDGES;
}
__global__ void k_fill(const int* __restrict__ ei) {
    int e = blockIdx.x * blockDim.x + threadIdx.x;
    if (e < N_EDGES) {
        int s = ei[e];
        int d = ei[N_EDGES + e];
        int p = atomicAdd(&g_cursor[d], 1);
        g_srce[p] = s;
    }
}

// ---------------- weight prepass: fp32 W[K,Nact] -> fp16 [KP][136] -----------
__global__ void k_prepW(const float* __restrict__ W,
                        __half* __restrict__ oh, int K, int Nact, int KP) {
    int i = blockIdx.x * 256 + threadIdx.x;
    if (i >= KP * 136) return;
    int k = i / 136, n = i - k * 136;
    float v = (k < K && n < Nact) ? W[(size_t)k * Nact + n] : 0.f;
    oh[i] = __float2half_rn(v);
}

// ---------------- shared GEMM plumbing ---------------------------------------
#define A_ST 40
#define B_ST 136
#define OFF_BH 5120            // A: 64*40*2 = 5120 B
#define STAGE_B 13824          // + B: 32*136*2 = 8704 B
#define GEMM_SMEM (2 * STAGE_B)

__device__ __forceinline__ uint32_t smem_u32(const void* p) {
    uint32_t a;
    asm("{ .reg .u64 t; cvta.to.shared.u64 t, %1; cvt.u32.u64 %0, t; }" : "=r"(a) : "l"(p));
    return a;
}
__device__ __forceinline__ void cpa16(uint32_t dst, const void* src) {
    asm volatile("cp.async.cg.shared.global [%0], [%1], 16;" :: "r"(dst), "l"(src));
}
__device__ __forceinline__ void cpa16z(uint32_t dst, const void* src, bool ok) {
    int sz = ok ? 16 : 0;
    asm volatile("cp.async.cg.shared.global [%0], [%1], 16, %2;" :: "r"(dst), "l"(src), "r"(sz));
}
#define CP_COMMIT() asm volatile("cp.async.commit_group;" ::: "memory")
#define CP_WAIT0()  asm volatile("cp.async.wait_group 0;" ::: "memory")

__device__ __forceinline__ void ldmx4(uint32_t* r, uint32_t addr) {
    asm volatile("ldmatrix.sync.aligned.m8n8.x4.shared.b16 {%0,%1,%2,%3}, [%4];"
        : "=r"(r[0]), "=r"(r[1]), "=r"(r[2]), "=r"(r[3]) : "r"(addr));
}
__device__ __forceinline__ void ldmx4t(uint32_t* r, uint32_t addr) {
    asm volatile("ldmatrix.sync.aligned.m8n8.x4.trans.shared.b16 {%0,%1,%2,%3}, [%4];"
        : "=r"(r[0]), "=r"(r[1]), "=r"(r[2]), "=r"(r[3]) : "r"(addr));
}
__device__ __forceinline__ void mma16816h(float* d, const uint32_t* a, const uint32_t* b) {
    asm volatile(
        "mma.sync.aligned.m16n8k16.row.col.f32.f16.f16.f32 "
        "{%0,%1,%2,%3}, {%4,%5,%6,%7}, {%8,%9}, {%0,%1,%2,%3};"
        : "+f"(d[0]), "+f"(d[1]), "+f"(d[2]), "+f"(d[3])
        : "r"(a[0]), "r"(a[1]), "r"(a[2]), "r"(a[3]), "r"(b[0]), "r"(b[1]));
}

// ---------------- GEMM1: fp32 A (LDG+convert), fp16 C stride 128 -------------
__global__ __launch_bounds__(256, 3) void k_gemm1(
    const float* __restrict__ A, const __half* __restrict__ Wh,
    __half* __restrict__ C, int M, int K)
{
    extern __shared__ char smp[];
    const uint32_t sbase = smem_u32(smp);

    const int tid = threadIdx.x, lane = tid & 31, warp = tid >> 5;
    const int wm = warp >> 2, wn = warp & 3;
    const int rowBase = blockIdx.x * 64;

    const int grp = lane >> 3;
    const uint32_t aLane  = (uint32_t)((((grp & 1) * 8 + (lane & 7)) * A_ST + (grp >> 1) * 8) * 2);
    const uint32_t bLaneT = (uint32_t)(((lane & 15) * B_ST) * 2) + (uint32_t)(wn * 64)
                          + (uint32_t)(((lane >> 4) & 1) * 16);

    float acc[2][4][4];
    #pragma unroll
    for (int i = 0; i < 2; i++)
        #pragma unroll
        for (int j = 0; j < 4; j++)
            #pragma unroll
            for (int r = 0; r < 4; r++) acc[i][j][r] = 0.f;

    const int NC = (K + 31) / 32;
    float aReg[8];

    auto copyB = [&](int c, uint32_t st) {
        const char* sH = (const char*)(Wh + (size_t)c * 32 * 136);
        uint32_t dH = st + OFF_BH;
        #pragma unroll
        for (int u = 0; u < 3; u++) {
            int i = u * 256 + tid;
            if (i < 544) cpa16(dH + (uint32_t)i * 16, sH + i * 16);
        }
    };
    auto loadA = [&](int c) {
        const int k0 = c * 32;
        #pragma unroll
        for (int u = 0; u < 8; u++) {
            int m = u * 8 + warp;
            int gm = rowBase + m, gk = k0 + lane;
            aReg[u] = (gm < M && gk < K) ? __ldg(&A[(size_t)gm * K + gk]) : 0.f;
        }
    };
    auto convA = [&](uint32_t st) {
        __half* ah = (__half*)(smp + (st - sbase));
        #pragma unroll
        for (int u = 0; u < 8; u++) {
            int m = u * 8 + warp;
            ah[m * A_ST + lane] = __float2half_rn(aReg[u]);
        }
    };

    copyB(0, sbase);
    CP_COMMIT();
    loadA(0);
    convA(sbase);
    CP_WAIT0();

    for (int c = 0; c < NC; c++) {
        __syncthreads();
        const uint32_t stN = sbase + (uint32_t)((c + 1) & 1) * STAGE_B;
        const bool more = (c + 1 < NC);
        if (more) copyB(c + 1, stN);
        CP_COMMIT();
        if (more) loadA(c + 1);

        const uint32_t st = sbase + (uint32_t)(c & 1) * STAGE_B;
        const uint32_t uAh = st, uBh = st + OFF_BH;
        #pragma unroll
        for (int ks = 0; ks < 2; ks++) {
            uint32_t bh[4][2];
            #pragma unroll
            for (int p = 0; p < 2; p++) {
                uint32_t r4[4];
                ldmx4t(r4, uBh + (uint32_t)(ks * 16 * B_ST * 2) + bLaneT + (uint32_t)(p * 32));
                bh[2 * p][0] = r4[0]; bh[2 * p][1] = r4[1];
                bh[2 * p + 1][0] = r4[2]; bh[2 * p + 1][1] = r4[3];
            }
            #pragma unroll
            for (int mt = 0; mt < 2; mt++) {
                uint32_t ao = aLane + (uint32_t)(((wm * 32 + mt * 16) * A_ST + ks * 16) * 2);
                uint32_t ah[4];
                ldmx4(ah, uAh + ao);
                #pragma unroll
                for (int nt = 0; nt < 4; nt++) mma16816h(acc[mt][nt], ah, bh[nt]);
            }
        }

        if (more) convA(stN);
        CP_WAIT0();
    }

    const int r = lane >> 2, cc = (lane & 3) * 2;
    #pragma unroll
    for (int mt = 0; mt < 2; mt++) {
        int m0 = rowBase + wm * 32 + mt * 16 + r;
        #pragma unroll
        for (int nt = 0; nt < 4; nt++) {
            int n0 = wn * 32 + nt * 8 + cc;
            if (m0 < M)
                *(__half2*)(C + (size_t)m0 * 128 + n0) = __floats2half2_rn(acc[mt][nt][0], acc[mt][nt][1]);
            if (m0 + 8 < M)
                *(__half2*)(C + (size_t)(m0 + 8) * 128 + n0) = __floats2half2_rn(acc[mt][nt][2], acc[mt][nt][3]);
        }
    }
}

// ---------------- GEMM2/3: fp16 A (pure cp.async), fp16 C --------------------
// C48: store stride 48 (layer 3) vs stride 128 (layer 2).
template<bool C48>
__global__ __launch_bounds__(256, 3) void k_gemm_h(
    const __half* __restrict__ A,   // [M,128] fp16
    const __half* __restrict__ Wh,
    __half* __restrict__ C, int M)
{
    extern __shared__ char smp[];
    const uint32_t sbase = smem_u32(smp);

    const int tid = threadIdx.x, lane = tid & 31, warp = tid >> 5;
    const int wm = warp >> 2, wn = warp & 3;
    const int rowBase = blockIdx.x * 64;

    const int grp = lane >> 3;
    const uint32_t aLane  = (uint32_t)((((grp & 1) * 8 + (lane & 7)) * A_ST + (grp >> 1) * 8) * 2);
    const uint32_t bLaneT = (uint32_t)(((lane & 15) * B_ST) * 2) + (uint32_t)(wn * 64)
                          + (uint32_t)(((lane >> 4) & 1) * 16);

    float acc[2][4][4];
    #pragma unroll
    for (int i = 0; i < 2; i++)
        #pragma unroll
        for (int j = 0; j < 4; j++)
            #pragma unroll
            for (int r = 0; r < 4; r++) acc[i][j][r] = 0.f;

    const int NC = 4;  // K = 128

    auto copyAB = [&](int c, uint32_t st) {
        // A: 64 rows x 32 halfs = 4 x 16B per row; one cp per thread
        int m = tid >> 2, j = tid & 3;
        int gm = rowBase + m;
        const char* srcA = (const char*)(A + (size_t)(gm < M ? gm : 0) * 128 + c * 32 + j * 8);
        cpa16z(st + (uint32_t)(m * (A_ST * 2) + j * 16), srcA, gm < M);
        // B: 544 x 16B
        const char* sH = (const char*)(Wh + (size_t)c * 32 * 136);
        uint32_t dH = st + OFF_BH;
        #pragma unroll
        for (int u = 0; u < 3; u++) {
            int i = u * 256 + tid;
            if (i < 544) cpa16(dH + (uint32_t)i * 16, sH + i * 16);
        }
    };

    copyAB(0, sbase);
    CP_COMMIT();
    CP_WAIT0();

    for (int c = 0; c < NC; c++) {
        __syncthreads();
        const uint32_t stN = sbase + (uint32_t)((c + 1) & 1) * STAGE_B;
        const bool more = (c + 1 < NC);
        if (more) copyAB(c + 1, stN);
        CP_COMMIT();

        const uint32_t st = sbase + (uint32_t)(c & 1) * STAGE_B;
        const uint32_t uAh = st, uBh = st + OFF_BH;
        #pragma unroll
        for (int ks = 0; ks < 2; ks++) {
            uint32_t bh[4][2];
            #pragma unroll
            for (int p = 0; p < 2; p++) {
                uint32_t r4[4];
                ldmx4t(r4, uBh + (uint32_t)(ks * 16 * B_ST * 2) + bLaneT + (uint32_t)(p * 32));
                bh[2 * p][0] = r4[0]; bh[2 * p][1] = r4[1];
                bh[2 * p + 1][0] = r4[2]; bh[2 * p + 1][1] = r4[3];
            }
            #pragma unroll
            for (int mt = 0; mt < 2; mt++) {
                uint32_t ao = aLane + (uint32_t)(((wm * 32 + mt * 16) * A_ST + ks * 16) * 2);
                uint32_t ah[4];
                ldmx4(ah, uAh + ao);
                #pragma unroll
                for (int nt = 0; nt < 4; nt++) mma16816h(acc[mt][nt], ah, bh[nt]);
            }
        }
        CP_WAIT0();
    }

    const int r = lane >> 2, cc = (lane & 3) * 2;
    #pragma unroll
    for (int mt = 0; mt < 2; mt++) {
        int m0 = rowBase + wm * 32 + mt * 16 + r;
        #pragma unroll
        for (int nt = 0; nt < 4; nt++) {
            int n0 = wn * 32 + nt * 8 + cc;
            if (C48) {
                if (n0 < 48) {
                    if (m0 < M)
                        *(__half2*)(C + (size_t)m0 * 48 + n0) = __floats2half2_rn(acc[mt][nt][0], acc[mt][nt][1]);
                    if (m0 + 8 < M)
                        *(__half2*)(C + (size_t)(m0 + 8) * 48 + n0) = __floats2half2_rn(acc[mt][nt][2], acc[mt][nt][3]);
                }
            } else {
                if (m0 < M)
                    *(__half2*)(C + (size_t)m0 * 128 + n0) = __floats2half2_rn(acc[mt][nt][0], acc[mt][nt][1]);
                if (m0 + 8 < M)
                    *(__half2*)(C + (size_t)(m0 + 8) * 128 + n0) = __floats2half2_rn(acc[mt][nt][2], acc[mt][nt][3]);
            }
        }
    }
}

// ---------------- aggregation (fp16 gather, fp32 accum, fp16 h out) ----------
template<bool RELU>
__global__ __launch_bounds__(128) void k_agg128h(const float* __restrict__ bias) {
    const __half* hw = g_bufH;          // stride 128 halfs
    __half* out = g_bufHB;              // stride 128 halfs
    __shared__ int   s_idx[4][32];
    __shared__ float s_wt [4][32];

    int w    = threadIdx.x >> 5;
    int lane = threadIdx.x & 31;
    int node = blockIdx.x * 4 + w;
    if (node >= N_NODES) return;

    int beg = g_rowptr[node];
    int end = g_rowptr[node + 1];
    float dd = g_dinv[node];

    float ax = 0.f, ay = 0.f, az = 0.f, aw = 0.f;

    for (int base = beg; base < end; base += 32) {
        int n = end - base; if (n > 32) n = 32;
        int si = 0; float swt = 0.f;
        if (lane < n) { si = g_srce[base + lane]; swt = g_dinv[si] * dd; }
        s_idx[w][lane] = si; s_wt[w][lane] = swt;
        __syncwarp();
        if (n == 32) {
            #pragma unroll 8
            for (int j = 0; j < 32; j++) {
                int ss = s_idx[w][j]; float ww = s_wt[w][j];
                uint2 raw = *(const uint2*)(hw + (size_t)ss * 128 + lane * 4);
                float2 f0 = __half22float2(*(__half2*)&raw.x);
                float2 f1 = __half22float2(*(__half2*)&raw.y);
                ax += f0.x * ww; ay += f0.y * ww; az += f1.x * ww; aw += f1.y * ww;
            }
        } else {
            for (int j = 0; j < n; j++) {
                int ss = s_idx[w][j]; float ww = s_wt[w][j];
                uint2 raw = *(const uint2*)(hw + (size_t)ss * 128 + lane * 4);
                float2 f0 = __half22float2(*(__half2*)&raw.x);
                float2 f1 = __half22float2(*(__half2*)&raw.y);
                ax += f0.x * ww; ay += f0.y * ww; az += f1.x * ww; aw += f1.y * ww;
            }
        }
        __syncwarp();
    }

    {   // self-loop
        float ww = dd * dd;
        uint2 raw = *(const uint2*)(hw + (size_t)node * 128 + lane * 4);
        float2 f0 = __half22float2(*(__half2*)&raw.x);
        float2 f1 = __half22float2(*(__half2*)&raw.y);
        ax += f0.x * ww; ay += f0.y * ww; az += f1.x * ww; aw += f1.y * ww;
    }
    float4 b = *(const float4*)(bias + lane * 4);
    ax += b.x; ay += b.y; az += b.z; aw += b.w;
    if (RELU) {
        ax = fmaxf(ax, 0.f); ay = fmaxf(ay, 0.f);
        az = fmaxf(az, 0.f); aw = fmaxf(aw, 0.f);
    }
    __half2 o0 = __floats2half2_rn(ax, ay);
    __half2 o1 = __floats2half2_rn(az, aw);
    uint2 pk = { *(uint32_t*)&o0, *(uint32_t*)&o1 };
    *(uint2*)(out + (size_t)node * 128 + lane * 4) = pk;
}

// final layer: gather fp16 stride-48 rows, fp32 out
__global__ __launch_bounds__(128) void k_agg47h(const float* __restrict__ bias,
                                                float* __restrict__ out) {
    const __half* hw = g_buf48;   // stride 48 halfs
    __shared__ int   s_idx[4][32];
    __shared__ float s_wt [4][32];

    int w    = threadIdx.x >> 5;
    int lane = threadIdx.x & 31;
    int node = blockIdx.x * 4 + w;
    if (node >= N_NODES) return;

    int beg = g_rowptr[node];
    int end = g_rowptr[node + 1];
    float dd = g_dinv[node];
    bool act = (lane < 24);       // lanes 0-23 cover 48 cols as half2

    float a0 = 0.f, a1 = 0.f;

    for (int base = beg; base < end; base += 32) {
        int n = end - base; if (n > 32) n = 32;
        int si = 0; float swt = 0.f;
        if (lane < n) { si = g_srce[base + lane]; swt = g_dinv[si] * dd; }
        s_idx[w][lane] = si; s_wt[w][lane] = swt;
        __syncwarp();
        for (int j = 0; j < n; j++) {
            int ss = s_idx[w][j]; float ww = s_wt[w][j];
            if (act) {
                uint32_t raw = *(const uint32_t*)(hw + (size_t)ss * 48 + lane * 2);
                float2 f = __half22float2(*(__half2*)&raw);
                a0 += f.x * ww; a1 += f.y * ww;
            }
        }
        __syncwarp();
    }
    {   // self-loop
        float ww = dd * dd;
        if (act) {
            uint32_t raw = *(const uint32_t*)(hw + (size_t)node * 48 + lane * 2);
            float2 f = __half22float2(*(__half2*)&raw);
            a0 += f.x * ww; a1 += f.y * ww;
        }
    }
    if (act) {
        int c0 = lane * 2;
        out[(size_t)node * OUT_C + c0] = a0 + bias[c0];
        if (c0 + 1 < OUT_C)
            out[(size_t)node * OUT_C + c0 + 1] = a1 + bias[c0 + 1];
    }
}

// ---------------- launch ------------------------------------------------
extern "C" void kernel_launch(void* const* d_in, const int* in_sizes, int n_in,
                              void* d_out, int out_size) {
    const float* x  = (const float*)d_in[0];
    const int*   ei = (const int*)  d_in[1];
    const float* W1 = (const float*)d_in[2];
    const float* b1 = (const float*)d_in[3];
    const float* W2 = (const float*)d_in[4];
    const float* b2 = (const float*)d_in[5];
    const float* W3 = (const float*)d_in[6];
    const float* b3 = (const float*)d_in[7];
    float* out = (float*)d_out;

    void *pH, *pHB, *p48, *p1h, *p2h, *p3h;
    cudaGetSymbolAddress(&pH,  g_bufH);
    cudaGetSymbolAddress(&pHB, g_bufHB);
    cudaGetSymbolAddress(&p48, g_buf48);
    cudaGetSymbolAddress(&p1h, g_W1h);
    cudaGetSymbolAddress(&p2h, g_W2h);
    cudaGetSymbolAddress(&p3h, g_W3h);

    cudaFuncSetAttribute((const void*)&k_gemm1,        cudaFuncAttributeMaxDynamicSharedMemorySize, GEMM_SMEM);
    cudaFuncSetAttribute((const void*)&k_gemm_h<false>, cudaFuncAttributeMaxDynamicSharedMemorySize, GEMM_SMEM);
    cudaFuncSetAttribute((const void*)&k_gemm_h<true>,  cudaFuncAttributeMaxDynamicSharedMemorySize, GEMM_SMEM);

    // one-time side stream + events
    static cudaStream_t s2 = nullptr;
    static cudaEvent_t evFork = nullptr, evSide = nullptr;
    if (!s2) {
        cudaStreamCreateWithFlags(&s2, cudaStreamNonBlocking);
        cudaEventCreateWithFlags(&evFork, cudaEventDisableTiming);
        cudaEventCreateWithFlags(&evSide, cudaEventDisableTiming);
    }

    const int NB = (N_NODES + 255) / 256;
    const int EB = (N_EDGES + 255) / 256;
    const int gemmGrid = (N_NODES + 63) / 64;    // 782
    const int aggGrid  = (N_NODES + 3) / 4;

    // fork side stream at t=0: full CSR build + weight prep 2/3
    cudaEventRecord(evFork, 0);
    cudaStreamWaitEvent(s2, evFork, 0);
    k_zero_cnt<<<NB, 256, 0, s2>>>();
    k_hist<<<EB, 256, 0, s2>>>(ei);
    k_scan1<<<NB, 256, 0, s2>>>();
    k_scan2<<<1, 256, 0, s2>>>(NB);
    k_scan3<<<NB, 256, 0, s2>>>();
    k_fill<<<EB, 256, 0, s2>>>(ei);
    k_prepW<<<(KP2 * 136 + 255) / 256, 256, 0, s2>>>(W2, (__half*)p2h, HID_C, HID_C, KP2);
    k_prepW<<<(KP3 * 136 + 255) / 256, 256, 0, s2>>>(W3, (__half*)p3h, HID_C, OUT_C, KP3);
    cudaEventRecord(evSide, s2);

    // main stream: GEMM1 immediately
    k_prepW<<<(KP1 * 136 + 255) / 256, 256>>>(W1, (__half*)p1h, IN_C, HID_C, KP1);
    k_gemm1<<<gemmGrid, 256, GEMM_SMEM>>>(x, (const __half*)p1h, (__half*)pH, N_NODES, IN_C);

    // join, then the rest
    cudaStreamWaitEvent(0, evSide, 0);
    k_agg128h<true><<<aggGrid, 128>>>(b1);
    k_gemm_h<false><<<gemmGrid, 256, GEMM_SMEM>>>((const __half*)pHB, (const __half*)p2h,
                                                  (__half*)pH, N_NODES);
    k_agg128h<true><<<aggGrid, 128>>>(b2);
    k_gemm_h<true><<<gemmGrid, 256, GEMM_SMEM>>>((const __half*)pHB, (const __half*)p3h,
                                                 (__half*)p48, N_NODES);
    k_agg47h<<<aggGrid, 128>>>(b3, out);
}